// round 3
// baseline (speedup 1.0000x reference)
#include <cuda_runtime.h>
#include <math.h>

// Problem dims
constexpr int ROWS = 8 * 1024;   // N*S = 8192
constexpr int E    = 768;
constexpr int E3   = 2304;
constexpr int FF   = 3072;

// Scratch (device globals: allocation-guard safe)
__device__ float g_h[(size_t)ROWS * E];
__device__ float g_qkv[(size_t)ROWS * E3];
__device__ float g_attn[(size_t)ROWS * E];
__device__ float g_x1[(size_t)ROWS * E];
__device__ float g_ff[(size_t)ROWS * FF];

// ---------------------------------------------------------------------------
// LayerNorm: one block per row (768 cols, 256 threads x 3 elems)
// ---------------------------------------------------------------------------
__global__ void __launch_bounds__(256) ln_kernel(const float* __restrict__ x,
                                                 const float* __restrict__ g,
                                                 const float* __restrict__ b,
                                                 float* __restrict__ out) {
    __shared__ float sh[9];
    int row = blockIdx.x;
    int tid = threadIdx.x;
    const float* xr = x + (size_t)row * E;
    float v0 = xr[tid], v1 = xr[tid + 256], v2 = xr[tid + 512];

    float s = v0 + v1 + v2;
    #pragma unroll
    for (int o = 16; o > 0; o >>= 1) s += __shfl_xor_sync(0xffffffffu, s, o);
    if ((tid & 31) == 0) sh[tid >> 5] = s;
    __syncthreads();
    if (tid == 0) {
        float t = 0.f;
        #pragma unroll
        for (int i = 0; i < 8; i++) t += sh[i];
        sh[8] = t * (1.0f / E);
    }
    __syncthreads();
    float mu = sh[8];
    __syncthreads();

    float d0 = v0 - mu, d1 = v1 - mu, d2 = v2 - mu;
    float s2 = d0 * d0 + d1 * d1 + d2 * d2;
    #pragma unroll
    for (int o = 16; o > 0; o >>= 1) s2 += __shfl_xor_sync(0xffffffffu, s2, o);
    if ((tid & 31) == 0) sh[tid >> 5] = s2;
    __syncthreads();
    if (tid == 0) {
        float t = 0.f;
        #pragma unroll
        for (int i = 0; i < 8; i++) t += sh[i];
        sh[8] = rsqrtf(t * (1.0f / E) + 1e-5f);
    }
    __syncthreads();
    float rs = sh[8];

    float* orow = out + (size_t)row * E;
    orow[tid]       = d0 * rs * g[tid]       + b[tid];
    orow[tid + 256] = d1 * rs * g[tid + 256] + b[tid + 256];
    orow[tid + 512] = d2 * rs * g[tid + 512] + b[tid + 512];
}

// ---------------------------------------------------------------------------
// Tiled SIMT GEMM: C[M,N] = A[M,K] @ B[K,N] + bias (+ epilogue)
// 128x128 block, BK=8, 256 threads, 8x8 per thread.
// MODE 0: +bias;  MODE 1: +bias+residual;  MODE 2: +bias, exact GELU
// ---------------------------------------------------------------------------
template <int MODE>
__global__ void __launch_bounds__(256) gemm_kernel(
    const float* __restrict__ A, const float* __restrict__ B,
    const float* __restrict__ bias, const float* __restrict__ res,
    float* __restrict__ C, int Ndim, int Kdim) {
    __shared__ float As[8][128];
    __shared__ float Bs[8][128];
    int tid = threadIdx.x;
    int m0 = blockIdx.y * 128, n0 = blockIdx.x * 128;
    int tr = tid >> 4, tc = tid & 15;

    float acc[8][8];
    #pragma unroll
    for (int i = 0; i < 8; i++)
        #pragma unroll
        for (int j = 0; j < 8; j++) acc[i][j] = 0.f;

    int arow = tid >> 1, akq = (tid & 1) << 2;
    int brow = tid >> 5, bcol = (tid & 31) << 2;

    for (int k0 = 0; k0 < Kdim; k0 += 8) {
        float4 av = *(const float4*)&A[(size_t)(m0 + arow) * Kdim + k0 + akq];
        As[akq + 0][arow] = av.x;
        As[akq + 1][arow] = av.y;
        As[akq + 2][arow] = av.z;
        As[akq + 3][arow] = av.w;
        float4 bv = *(const float4*)&B[(size_t)(k0 + brow) * Ndim + n0 + bcol];
        *(float4*)&Bs[brow][bcol] = bv;
        __syncthreads();
        #pragma unroll
        for (int kk = 0; kk < 8; kk++) {
            float a[8], bb[8];
            #pragma unroll
            for (int i = 0; i < 8; i++) a[i] = As[kk][i * 16 + tr];
            #pragma unroll
            for (int j = 0; j < 8; j++) bb[j] = Bs[kk][j * 16 + tc];
            #pragma unroll
            for (int i = 0; i < 8; i++)
                #pragma unroll
                for (int j = 0; j < 8; j++) acc[i][j] += a[i] * bb[j];
        }
        __syncthreads();
    }

    #pragma unroll
    for (int i = 0; i < 8; i++) {
        int row = m0 + i * 16 + tr;
        #pragma unroll
        for (int j = 0; j < 8; j++) {
            int col = n0 + j * 16 + tc;
            float v = acc[i][j] + bias[col];
            if (MODE == 2) v = 0.5f * v * (1.0f + erff(v * 0.70710678118f));
            if (MODE == 1) v += res[(size_t)row * Ndim + col];
            C[(size_t)row * Ndim + col] = v;
        }
    }
}

// ---------------------------------------------------------------------------
// Flash attention: grid (16 q-tiles, 96 n*h), 128 threads.
// Each CTA: 64 q-rows of one (n,h); iterate causal k-tiles with online softmax.
// Thread (r = tid/4 in [0,32), cq = tid&3) owns rows {r, r+32}, cols {cq+4j}.
// ---------------------------------------------------------------------------
constexpr int TS = 65;  // padded smem tile stride

__global__ void __launch_bounds__(128) attn_kernel() {
    extern __shared__ float sm[];
    float* Qs = sm;
    float* Ks = Qs + 64 * TS;
    float* Vs = Ks + 64 * TS;
    float* Ps = Vs + 64 * TS;

    int qt = blockIdx.x;
    int nh = blockIdx.y;
    int h = nh % 12, n = nh / 12;
    int row0 = n * 1024 + qt * 64;
    int tid = threadIdx.x;
    int cq = tid & 3, r = tid >> 2;
    int hoff = h * 64;

    // Load Q tile
    for (int i = tid; i < 64 * 16; i += 128) {
        int rr = i >> 4, c4 = (i & 15) << 2;
        float4 v = *(const float4*)&g_qkv[(size_t)(row0 + rr) * 2304 + hoff + c4];
        float* dst = &Qs[rr * TS + c4];
        dst[0] = v.x; dst[1] = v.y; dst[2] = v.z; dst[3] = v.w;
    }

    float m0v = -1e30f, m1v = -1e30f, l0 = 0.f, l1 = 0.f;
    float o0[16], o1[16];
    #pragma unroll
    for (int i = 0; i < 16; i++) { o0[i] = 0.f; o1[i] = 0.f; }

    for (int t = 0; t <= qt; ++t) {
        int krow0 = n * 1024 + t * 64;
        for (int i = tid; i < 64 * 16; i += 128) {
            int rr = i >> 4, c4 = (i & 15) << 2;
            size_t base = (size_t)(krow0 + rr) * 2304 + hoff + c4;
            float4 kv = *(const float4*)&g_qkv[base + 768];
            float* dk = &Ks[rr * TS + c4];
            dk[0] = kv.x; dk[1] = kv.y; dk[2] = kv.z; dk[3] = kv.w;
            float4 vv = *(const float4*)&g_qkv[base + 1536];
            float* dv = &Vs[rr * TS + c4];
            dv[0] = vv.x; dv[1] = vv.y; dv[2] = vv.z; dv[3] = vv.w;
        }
        __syncthreads();

        // Scores: S = Q K^T
        float s0[16], s1[16];
        #pragma unroll
        for (int j = 0; j < 16; j++) { s0[j] = 0.f; s1[j] = 0.f; }
        #pragma unroll 4
        for (int d = 0; d < 64; ++d) {
            float q0 = Qs[r * TS + d];
            float q1 = Qs[(r + 32) * TS + d];
            #pragma unroll
            for (int j = 0; j < 16; j++) {
                float kv = Ks[(cq + 4 * j) * TS + d];
                s0[j] += q0 * kv;
                s1[j] += q1 * kv;
            }
        }

        // Scale + causal mask (diagonal tile only)
        bool diag = (t == qt);
        #pragma unroll
        for (int j = 0; j < 16; j++) {
            int col = cq + 4 * j;
            s0[j] = (diag && col > r)      ? -1e30f : s0[j] * 0.125f;
            s1[j] = (diag && col > r + 32) ? -1e30f : s1[j] * 0.125f;
        }

        // Online softmax
        float mx0 = -1e30f, mx1 = -1e30f;
        #pragma unroll
        for (int j = 0; j < 16; j++) {
            mx0 = fmaxf(mx0, s0[j]);
            mx1 = fmaxf(mx1, s1[j]);
        }
        mx0 = fmaxf(mx0, __shfl_xor_sync(0xffffffffu, mx0, 1));
        mx0 = fmaxf(mx0, __shfl_xor_sync(0xffffffffu, mx0, 2));
        mx1 = fmaxf(mx1, __shfl_xor_sync(0xffffffffu, mx1, 1));
        mx1 = fmaxf(mx1, __shfl_xor_sync(0xffffffffu, mx1, 2));

        float nm0 = fmaxf(m0v, mx0), nm1 = fmaxf(m1v, mx1);
        float f0 = __expf(m0v - nm0), f1 = __expf(m1v - nm1);
        float ls0 = 0.f, ls1 = 0.f;
        #pragma unroll
        for (int j = 0; j < 16; j++) {
            float p0 = __expf(s0[j] - nm0); s0[j] = p0; ls0 += p0;
            float p1 = __expf(s1[j] - nm1); s1[j] = p1; ls1 += p1;
        }
        ls0 += __shfl_xor_sync(0xffffffffu, ls0, 1);
        ls0 += __shfl_xor_sync(0xffffffffu, ls0, 2);
        ls1 += __shfl_xor_sync(0xffffffffu, ls1, 1);
        ls1 += __shfl_xor_sync(0xffffffffu, ls1, 2);
        l0 = l0 * f0 + ls0;
        l1 = l1 * f1 + ls1;
        m0v = nm0; m1v = nm1;
        #pragma unroll
        for (int i = 0; i < 16; i++) { o0[i] *= f0; o1[i] *= f1; }

        // P to smem
        #pragma unroll
        for (int j = 0; j < 16; j++) {
            Ps[r * TS + cq + 4 * j] = s0[j];
            Ps[(r + 32) * TS + cq + 4 * j] = s1[j];
        }
        __syncthreads();

        // O += P V
        #pragma unroll 4
        for (int j = 0; j < 64; ++j) {
            float p0 = Ps[r * TS + j];
            float p1 = Ps[(r + 32) * TS + j];
            #pragma unroll
            for (int i = 0; i < 16; i++) {
                float vv = Vs[j * TS + cq + 4 * i];
                o0[i] += p0 * vv;
                o1[i] += p1 * vv;
            }
        }
        __syncthreads();
    }

    float inv0 = 1.f / l0, inv1 = 1.f / l1;
    size_t ob0 = (size_t)(row0 + r) * 768 + hoff + cq;
    size_t ob1 = (size_t)(row0 + r + 32) * 768 + hoff + cq;
    #pragma unroll
    for (int i = 0; i < 16; i++) {
        g_attn[ob0 + 4 * i] = o0[i] * inv0;
        g_attn[ob1 + 4 * i] = o1[i] * inv1;
    }
}

// ---------------------------------------------------------------------------
extern "C" void kernel_launch(void* const* d_in, const int* in_sizes, int n_in,
                              void* d_out, int out_size) {
    const float* x      = (const float*)d_in[0];
    const float* ln1_g  = (const float*)d_in[1];
    const float* ln1_b  = (const float*)d_in[2];
    const float* ln2_g  = (const float*)d_in[3];
    const float* ln2_b  = (const float*)d_in[4];
    const float* w_attn = (const float*)d_in[5];
    const float* b_attn = (const float*)d_in[6];
    const float* w_proj = (const float*)d_in[7];
    const float* b_proj = (const float*)d_in[8];
    const float* w_fc   = (const float*)d_in[9];
    const float* b_fc   = (const float*)d_in[10];
    const float* w_fc2  = (const float*)d_in[11];
    const float* b_fc2  = (const float*)d_in[12];
    float* out = (float*)d_out;

    float *p_h, *p_qkv, *p_attn, *p_x1, *p_ff;
    cudaGetSymbolAddress((void**)&p_h, g_h);
    cudaGetSymbolAddress((void**)&p_qkv, g_qkv);
    cudaGetSymbolAddress((void**)&p_attn, g_attn);
    cudaGetSymbolAddress((void**)&p_x1, g_x1);
    cudaGetSymbolAddress((void**)&p_ff, g_ff);

    // 1. LN1
    ln_kernel<<<ROWS, 256>>>(x, ln1_g, ln1_b, p_h);
    // 2. qkv = h @ w_attn + b_attn       [8192 x 2304], K=768
    gemm_kernel<0><<<dim3(18, 64), 256>>>(p_h, w_attn, b_attn, nullptr, p_qkv, 2304, 768);
    // 3. causal flash attention
    cudaFuncSetAttribute(attn_kernel, cudaFuncAttributeMaxDynamicSharedMemorySize, 4 * 64 * TS * 4);
    attn_kernel<<<dim3(16, 96), 128, 4 * 64 * TS * 4>>>();
    // 4. x1 = x + attn @ w_proj + b_proj [8192 x 768], K=768
    gemm_kernel<1><<<dim3(6, 64), 256>>>(p_attn, w_proj, b_proj, x, p_x1, 768, 768);
    // 5. LN2
    ln_kernel<<<ROWS, 256>>>(p_x1, ln2_g, ln2_b, p_h);
    // 6. ff = gelu(h2 @ w_fc + b_fc)     [8192 x 3072], K=768
    gemm_kernel<2><<<dim3(24, 64), 256>>>(p_h, w_fc, b_fc, nullptr, p_ff, 3072, 768);
    // 7. out = x1 + ff @ w_fc2 + b_fc2   [8192 x 768], K=3072
    gemm_kernel<1><<<dim3(6, 64), 256>>>(p_ff, w_fc2, b_fc2, p_x1, out, 768, 3072);
}

// round 6
// speedup vs baseline: 2.0321x; 2.0321x over previous
#include <cuda_runtime.h>
#include <cuda_bf16.h>
#include <math.h>
#include <stdint.h>

// Problem dims
constexpr int ROWS = 8 * 1024;   // N*S = 8192
constexpr int E    = 768;
constexpr int E3   = 2304;
constexpr int FF   = 3072;

// ---------------------------------------------------------------------------
// Scratch (device globals: allocation-guard safe)
// ---------------------------------------------------------------------------
__device__ float g_qkv[(size_t)ROWS * E3];
__device__ float g_x1[(size_t)ROWS * E];
__device__ __nv_bfloat16 g_h_hi[(size_t)ROWS * E];
__device__ __nv_bfloat16 g_h_lo[(size_t)ROWS * E];
__device__ __nv_bfloat16 g_attn_hi[(size_t)ROWS * E];
__device__ __nv_bfloat16 g_attn_lo[(size_t)ROWS * E];
__device__ __nv_bfloat16 g_ff_hi[(size_t)ROWS * FF];
__device__ __nv_bfloat16 g_ff_lo[(size_t)ROWS * FF];
// Transposed+split weights: [N, K] bf16
__device__ __nv_bfloat16 g_wqkv_hi[(size_t)E3 * E];
__device__ __nv_bfloat16 g_wqkv_lo[(size_t)E3 * E];
__device__ __nv_bfloat16 g_wproj_hi[(size_t)E * E];
__device__ __nv_bfloat16 g_wproj_lo[(size_t)E * E];
__device__ __nv_bfloat16 g_wfc_hi[(size_t)FF * E];
__device__ __nv_bfloat16 g_wfc_lo[(size_t)FF * E];
__device__ __nv_bfloat16 g_wfc2_hi[(size_t)E * FF];
__device__ __nv_bfloat16 g_wfc2_lo[(size_t)E * FF];

// ---------------------------------------------------------------------------
// Helpers (baseline compute_103 PTX only: cp.async + mma.sync, no tcgen05)
// ---------------------------------------------------------------------------
__device__ __forceinline__ uint32_t smem_u32(const void* p) {
    uint32_t a;
    asm("{ .reg .u64 t; cvta.to.shared.u64 t, %1; cvt.u32.u64 %0, t; }" : "=r"(a) : "l"(p));
    return a;
}

#define CP_ASYNC16(dst, src) asm volatile("cp.async.cg.shared.global [%0], [%1], 16;" :: "r"(dst), "l"(src))
#define CP_COMMIT()          asm volatile("cp.async.commit_group;" ::: "memory")
#define CP_WAIT(n)           asm volatile("cp.async.wait_group %0;" :: "n"(n) : "memory")

#define MMA16816(d, a, b) \
    asm volatile( \
        "mma.sync.aligned.m16n8k16.row.col.f32.bf16.bf16.f32 " \
        "{%0,%1,%2,%3}, {%4,%5,%6,%7}, {%8,%9}, {%0,%1,%2,%3};" \
        : "+f"((d)[0]), "+f"((d)[1]), "+f"((d)[2]), "+f"((d)[3]) \
        : "r"((a)[0]), "r"((a)[1]), "r"((a)[2]), "r"((a)[3]), \
          "r"((b)[0]), "r"((b)[1]))

__device__ __forceinline__ uint32_t ld32(const __nv_bfloat16* p) {
    return *(const uint32_t*)p;
}

__device__ __forceinline__ void split_store(__nv_bfloat16* hi, __nv_bfloat16* lo,
                                            size_t idx, float v) {
    __nv_bfloat16 h = __float2bfloat16(v);
    hi[idx] = h;
    lo[idx] = __float2bfloat16(v - __bfloat162float(h));
}

// ---------------------------------------------------------------------------
// LayerNorm -> split bf16 (hi/lo)
// ---------------------------------------------------------------------------
__global__ void __launch_bounds__(256) ln_kernel(const float* __restrict__ x,
                                                 const float* __restrict__ g,
                                                 const float* __restrict__ b,
                                                 __nv_bfloat16* __restrict__ ohi,
                                                 __nv_bfloat16* __restrict__ olo) {
    __shared__ float sh[9];
    int row = blockIdx.x;
    int tid = threadIdx.x;
    const float* xr = x + (size_t)row * E;
    float v0 = xr[tid], v1 = xr[tid + 256], v2 = xr[tid + 512];

    float s = v0 + v1 + v2;
    #pragma unroll
    for (int o = 16; o > 0; o >>= 1) s += __shfl_xor_sync(0xffffffffu, s, o);
    if ((tid & 31) == 0) sh[tid >> 5] = s;
    __syncthreads();
    if (tid == 0) {
        float t = 0.f;
        #pragma unroll
        for (int i = 0; i < 8; i++) t += sh[i];
        sh[8] = t * (1.0f / E);
    }
    __syncthreads();
    float mu = sh[8];
    __syncthreads();

    float d0 = v0 - mu, d1 = v1 - mu, d2 = v2 - mu;
    float s2 = d0 * d0 + d1 * d1 + d2 * d2;
    #pragma unroll
    for (int o = 16; o > 0; o >>= 1) s2 += __shfl_xor_sync(0xffffffffu, s2, o);
    if ((tid & 31) == 0) sh[tid >> 5] = s2;
    __syncthreads();
    if (tid == 0) {
        float t = 0.f;
        #pragma unroll
        for (int i = 0; i < 8; i++) t += sh[i];
        sh[8] = rsqrtf(t * (1.0f / E) + 1e-5f);
    }
    __syncthreads();
    float rs = sh[8];

    size_t rb = (size_t)row * E;
    split_store(ohi, olo, rb + tid,       d0 * rs * g[tid]       + b[tid]);
    split_store(ohi, olo, rb + tid + 256, d1 * rs * g[tid + 256] + b[tid + 256]);
    split_store(ohi, olo, rb + tid + 512, d2 * rs * g[tid + 512] + b[tid + 512]);
}

// ---------------------------------------------------------------------------
// Weight transpose + split: w[K,N] fp32 -> ohi/olo[N,K] bf16
// ---------------------------------------------------------------------------
__global__ void __launch_bounds__(256) wsplit_kernel(const float* __restrict__ w,
                                                     __nv_bfloat16* __restrict__ ohi,
                                                     __nv_bfloat16* __restrict__ olo,
                                                     int K, int N) {
    __shared__ float t[32][33];
    int n0 = blockIdx.x * 32, k0 = blockIdx.y * 32;
    int tx = threadIdx.x, ty = threadIdx.y;
    #pragma unroll
    for (int j = 0; j < 32; j += 8)
        t[ty + j][tx] = w[(size_t)(k0 + ty + j) * N + n0 + tx];
    __syncthreads();
    #pragma unroll
    for (int j = 0; j < 32; j += 8) {
        float v = t[tx][ty + j];
        split_store(ohi, olo, (size_t)(n0 + ty + j) * K + k0 + tx, v);
    }
}

// ---------------------------------------------------------------------------
// mma.sync split-bf16 GEMM: C[M,N] = (Ahi+Alo)[M,K] @ (Bhi+Blo)[N,K]^T + bias
// 3 HMMA products (hh + hl + lh) give ~16-bit effective input mantissa.
// CTA 128x128, BK=32, 8 warps (4 along M x 2 along N), warp tile 32x64.
// 3-stage cp.async pipeline. SMEM rows padded to 80B (conflict-free LDS).
// MODE 0: fp32 +bias;  MODE 1: fp32 +bias+residual;  MODE 2: +bias, GELU -> hi/lo bf16
// ---------------------------------------------------------------------------
constexpr int GBK = 32;
constexpr int TPAD = 40;                       // padded row stride (elements) = 80B
constexpr int TILE_B = 128 * TPAD * 2;         // one subtile: 10240 B
constexpr int STAGE_B = 4 * TILE_B;            // Ah, Al, Bh, Bl: 40960 B
constexpr size_t GEMM_SMEM = 3 * STAGE_B;      // 122880 B

template <int MODE>
__global__ void __launch_bounds__(256) gemm_mma(
    const __nv_bfloat16* __restrict__ Ahi, const __nv_bfloat16* __restrict__ Alo,
    const __nv_bfloat16* __restrict__ Bhi, const __nv_bfloat16* __restrict__ Blo,
    const float* __restrict__ bias, const float* __restrict__ res,
    float* __restrict__ C, __nv_bfloat16* __restrict__ Chi, __nv_bfloat16* __restrict__ Clo,
    int Ndim, int Kdim) {
    extern __shared__ __align__(16) char smem[];
    uint32_t sb = smem_u32(smem);
    int tid = threadIdx.x, wid = tid >> 5, lane = tid & 31;
    int wm = wid & 3, wn = wid >> 2;           // warp grid 4 (M) x 2 (N)
    int m0 = blockIdx.y * 128, n0 = blockIdx.x * 128;
    int r = lane >> 2, c2 = (lane & 3) * 2;

    float acc[2][8][4];
    #pragma unroll
    for (int mi = 0; mi < 2; mi++)
        #pragma unroll
        for (int ni = 0; ni < 8; ni++)
            #pragma unroll
            for (int q = 0; q < 4; q++) acc[mi][ni][q] = 0.f;

    const __nv_bfloat16* srcs[4] = {Ahi, Alo, Bhi, Blo};
    int rowbase[2] = {m0, n0};

    // 2048 16B chunks per stage (4 subtiles x 128 rows x 4 chunks), 8/thread
    auto load_stage = [&](int it, int buf) {
        int k0 = it * GBK;
        #pragma unroll
        for (int i = 0; i < 8; i++) {
            int ch = i * 256 + tid;
            int s = ch >> 9, cc = ch & 511;
            int row = cc >> 2, kc = cc & 3;
            uint32_t dst = sb + buf * STAGE_B + s * TILE_B + row * 80 + kc * 16;
            const __nv_bfloat16* src =
                srcs[s] + (size_t)(rowbase[s >> 1] + row) * Kdim + k0 + kc * 8;
            CP_ASYNC16(dst, src);
        }
        CP_COMMIT();
    };

    load_stage(0, 0);
    load_stage(1, 1);

    int niter = Kdim / GBK;
    for (int it = 0; it < niter; ++it) {
        int buf = it % 3;
        if (it + 1 < niter) CP_WAIT(1); else CP_WAIT(0);
        __syncthreads();
        if (it + 2 < niter) load_stage(it + 2, (it + 2) % 3);

        const __nv_bfloat16* Ash = (const __nv_bfloat16*)(smem + buf * STAGE_B);
        const __nv_bfloat16* Asl = (const __nv_bfloat16*)(smem + buf * STAGE_B + TILE_B);
        const __nv_bfloat16* Bsh = (const __nv_bfloat16*)(smem + buf * STAGE_B + 2 * TILE_B);
        const __nv_bfloat16* Bsl = (const __nv_bfloat16*)(smem + buf * STAGE_B + 3 * TILE_B);

        #pragma unroll
        for (int ks = 0; ks < 2; ks++) {
            uint32_t ah[2][4], al[2][4], bh[8][2], bl[8][2];
            #pragma unroll
            for (int mi = 0; mi < 2; mi++) {
                int off = (wm * 32 + mi * 16 + r) * TPAD + ks * 16 + c2;
                ah[mi][0] = ld32(Ash + off);
                ah[mi][1] = ld32(Ash + off + 8 * TPAD);
                ah[mi][2] = ld32(Ash + off + 8);
                ah[mi][3] = ld32(Ash + off + 8 * TPAD + 8);
                al[mi][0] = ld32(Asl + off);
                al[mi][1] = ld32(Asl + off + 8 * TPAD);
                al[mi][2] = ld32(Asl + off + 8);
                al[mi][3] = ld32(Asl + off + 8 * TPAD + 8);
            }
            #pragma unroll
            for (int ni = 0; ni < 8; ni++) {
                int off = (wn * 64 + ni * 8 + r) * TPAD + ks * 16 + c2;
                bh[ni][0] = ld32(Bsh + off);
                bh[ni][1] = ld32(Bsh + off + 8);
                bl[ni][0] = ld32(Bsl + off);
                bl[ni][1] = ld32(Bsl + off + 8);
            }
            // product hh
            #pragma unroll
            for (int ni = 0; ni < 8; ni++)
                #pragma unroll
                for (int mi = 0; mi < 2; mi++)
                    MMA16816(acc[mi][ni], ah[mi], bh[ni]);
            // product hl
            #pragma unroll
            for (int ni = 0; ni < 8; ni++)
                #pragma unroll
                for (int mi = 0; mi < 2; mi++)
                    MMA16816(acc[mi][ni], ah[mi], bl[ni]);
            // product lh
            #pragma unroll
            for (int ni = 0; ni < 8; ni++)
                #pragma unroll
                for (int mi = 0; mi < 2; mi++)
                    MMA16816(acc[mi][ni], al[mi], bh[ni]);
        }
        __syncthreads();
    }

    // Epilogue: direct register writeout, fused bias/residual/GELU/split
    #pragma unroll
    for (int mi = 0; mi < 2; mi++) {
        #pragma unroll
        for (int ni = 0; ni < 8; ni++) {
            int row = m0 + wm * 32 + mi * 16 + r;
            int col = n0 + wn * 64 + ni * 8 + c2;
            float2 bv = *(const float2*)&bias[col];
            #pragma unroll
            for (int half = 0; half < 2; half++) {
                int rr = row + half * 8;
                float v0 = acc[mi][ni][half * 2 + 0] + bv.x;
                float v1 = acc[mi][ni][half * 2 + 1] + bv.y;
                size_t gi = (size_t)rr * Ndim + col;
                if (MODE == 2) {
                    v0 = 0.5f * v0 * (1.0f + erff(v0 * 0.70710678118f));
                    v1 = 0.5f * v1 * (1.0f + erff(v1 * 0.70710678118f));
                    __nv_bfloat16 h0 = __float2bfloat16(v0);
                    __nv_bfloat16 h1 = __float2bfloat16(v1);
                    __nv_bfloat16 l0 = __float2bfloat16(v0 - __bfloat162float(h0));
                    __nv_bfloat16 l1 = __float2bfloat16(v1 - __bfloat162float(h1));
                    *(__nv_bfloat162*)&Chi[gi] = __nv_bfloat162(h0, h1);
                    *(__nv_bfloat162*)&Clo[gi] = __nv_bfloat162(l0, l1);
                } else {
                    if (MODE == 1) {
                        float2 rv = *(const float2*)&res[gi];
                        v0 += rv.x; v1 += rv.y;
                    }
                    *(float2*)&C[gi] = make_float2(v0, v1);
                }
            }
        }
    }
}

// ---------------------------------------------------------------------------
// Flash attention (SIMT fp32), outputs split bf16
// ---------------------------------------------------------------------------
constexpr int TS = 65;

__global__ void __launch_bounds__(128) attn_kernel() {
    extern __shared__ float sm[];
    float* Qs = sm;
    float* Ks = Qs + 64 * TS;
    float* Vs = Ks + 64 * TS;
    float* Ps = Vs + 64 * TS;

    int qt = blockIdx.x;
    int nh = blockIdx.y;
    int h = nh % 12, n = nh / 12;
    int row0 = n * 1024 + qt * 64;
    int tid = threadIdx.x;
    int cq = tid & 3, r = tid >> 2;
    int hoff = h * 64;

    for (int i = tid; i < 64 * 16; i += 128) {
        int rr = i >> 4, c4 = (i & 15) << 2;
        float4 v = *(const float4*)&g_qkv[(size_t)(row0 + rr) * 2304 + hoff + c4];
        float* dst = &Qs[rr * TS + c4];
        dst[0] = v.x; dst[1] = v.y; dst[2] = v.z; dst[3] = v.w;
    }

    float m0v = -1e30f, m1v = -1e30f, l0 = 0.f, l1 = 0.f;
    float o0[16], o1[16];
    #pragma unroll
    for (int i = 0; i < 16; i++) { o0[i] = 0.f; o1[i] = 0.f; }

    for (int t = 0; t <= qt; ++t) {
        int krow0 = n * 1024 + t * 64;
        for (int i = tid; i < 64 * 16; i += 128) {
            int rr = i >> 4, c4 = (i & 15) << 2;
            size_t base = (size_t)(krow0 + rr) * 2304 + hoff + c4;
            float4 kv = *(const float4*)&g_qkv[base + 768];
            float* dk = &Ks[rr * TS + c4];
            dk[0] = kv.x; dk[1] = kv.y; dk[2] = kv.z; dk[3] = kv.w;
            float4 vv = *(const float4*)&g_qkv[base + 1536];
            float* dv = &Vs[rr * TS + c4];
            dv[0] = vv.x; dv[1] = vv.y; dv[2] = vv.z; dv[3] = vv.w;
        }
        __syncthreads();

        float s0[16], s1[16];
        #pragma unroll
        for (int j = 0; j < 16; j++) { s0[j] = 0.f; s1[j] = 0.f; }
        #pragma unroll 4
        for (int d = 0; d < 64; ++d) {
            float q0 = Qs[r * TS + d];
            float q1 = Qs[(r + 32) * TS + d];
            #pragma unroll
            for (int j = 0; j < 16; j++) {
                float kv = Ks[(cq + 4 * j) * TS + d];
                s0[j] += q0 * kv;
                s1[j] += q1 * kv;
            }
        }

        bool diag = (t == qt);
        #pragma unroll
        for (int j = 0; j < 16; j++) {
            int col = cq + 4 * j;
            s0[j] = (diag && col > r)      ? -1e30f : s0[j] * 0.125f;
            s1[j] = (diag && col > r + 32) ? -1e30f : s1[j] * 0.125f;
        }

        float mx0 = -1e30f, mx1 = -1e30f;
        #pragma unroll
        for (int j = 0; j < 16; j++) {
            mx0 = fmaxf(mx0, s0[j]);
            mx1 = fmaxf(mx1, s1[j]);
        }
        mx0 = fmaxf(mx0, __shfl_xor_sync(0xffffffffu, mx0, 1));
        mx0 = fmaxf(mx0, __shfl_xor_sync(0xffffffffu, mx0, 2));
        mx1 = fmaxf(mx1, __shfl_xor_sync(0xffffffffu, mx1, 1));
        mx1 = fmaxf(mx1, __shfl_xor_sync(0xffffffffu, mx1, 2));

        float nm0 = fmaxf(m0v, mx0), nm1 = fmaxf(m1v, mx1);
        float f0 = __expf(m0v - nm0), f1 = __expf(m1v - nm1);
        float ls0 = 0.f, ls1 = 0.f;
        #pragma unroll
        for (int j = 0; j < 16; j++) {
            float p0 = __expf(s0[j] - nm0); s0[j] = p0; ls0 += p0;
            float p1 = __expf(s1[j] - nm1); s1[j] = p1; ls1 += p1;
        }
        ls0 += __shfl_xor_sync(0xffffffffu, ls0, 1);
        ls0 += __shfl_xor_sync(0xffffffffu, ls0, 2);
        ls1 += __shfl_xor_sync(0xffffffffu, ls1, 1);
        ls1 += __shfl_xor_sync(0xffffffffu, ls1, 2);
        l0 = l0 * f0 + ls0;
        l1 = l1 * f1 + ls1;
        m0v = nm0; m1v = nm1;
        #pragma unroll
        for (int i = 0; i < 16; i++) { o0[i] *= f0; o1[i] *= f1; }

        #pragma unroll
        for (int j = 0; j < 16; j++) {
            Ps[r * TS + cq + 4 * j] = s0[j];
            Ps[(r + 32) * TS + cq + 4 * j] = s1[j];
        }
        __syncthreads();

        #pragma unroll 4
        for (int j = 0; j < 64; ++j) {
            float p0 = Ps[r * TS + j];
            float p1 = Ps[(r + 32) * TS + j];
            #pragma unroll
            for (int i = 0; i < 16; i++) {
                float vv = Vs[j * TS + cq + 4 * i];
                o0[i] += p0 * vv;
                o1[i] += p1 * vv;
            }
        }
        __syncthreads();
    }

    float inv0 = 1.f / l0, inv1 = 1.f / l1;
    size_t ob0 = (size_t)(row0 + r) * 768 + hoff + cq;
    size_t ob1 = (size_t)(row0 + r + 32) * 768 + hoff + cq;
    #pragma unroll
    for (int i = 0; i < 16; i++) {
        split_store(g_attn_hi, g_attn_lo, ob0 + 4 * i, o0[i] * inv0);
        split_store(g_attn_hi, g_attn_lo, ob1 + 4 * i, o1[i] * inv1);
    }
}

// ---------------------------------------------------------------------------
extern "C" void kernel_launch(void* const* d_in, const int* in_sizes, int n_in,
                              void* d_out, int out_size) {
    const float* x      = (const float*)d_in[0];
    const float* ln1_g  = (const float*)d_in[1];
    const float* ln1_b  = (const float*)d_in[2];
    const float* ln2_g  = (const float*)d_in[3];
    const float* ln2_b  = (const float*)d_in[4];
    const float* w_attn = (const float*)d_in[5];
    const float* b_attn = (const float*)d_in[6];
    const float* w_proj = (const float*)d_in[7];
    const float* b_proj = (const float*)d_in[8];
    const float* w_fc   = (const float*)d_in[9];
    const float* b_fc   = (const float*)d_in[10];
    const float* w_fc2  = (const float*)d_in[11];
    const float* b_fc2  = (const float*)d_in[12];
    float* out = (float*)d_out;

    float *p_qkv, *p_x1;
    __nv_bfloat16 *p_hhi, *p_hlo, *p_ahi, *p_alo, *p_fhi, *p_flo;
    __nv_bfloat16 *p_wqh, *p_wql, *p_wph, *p_wpl, *p_wfh, *p_wfl, *p_w2h, *p_w2l;
    cudaGetSymbolAddress((void**)&p_qkv, g_qkv);
    cudaGetSymbolAddress((void**)&p_x1, g_x1);
    cudaGetSymbolAddress((void**)&p_hhi, g_h_hi);
    cudaGetSymbolAddress((void**)&p_hlo, g_h_lo);
    cudaGetSymbolAddress((void**)&p_ahi, g_attn_hi);
    cudaGetSymbolAddress((void**)&p_alo, g_attn_lo);
    cudaGetSymbolAddress((void**)&p_fhi, g_ff_hi);
    cudaGetSymbolAddress((void**)&p_flo, g_ff_lo);
    cudaGetSymbolAddress((void**)&p_wqh, g_wqkv_hi);
    cudaGetSymbolAddress((void**)&p_wql, g_wqkv_lo);
    cudaGetSymbolAddress((void**)&p_wph, g_wproj_hi);
    cudaGetSymbolAddress((void**)&p_wpl, g_wproj_lo);
    cudaGetSymbolAddress((void**)&p_wfh, g_wfc_hi);
    cudaGetSymbolAddress((void**)&p_wfl, g_wfc_lo);
    cudaGetSymbolAddress((void**)&p_w2h, g_wfc2_hi);
    cudaGetSymbolAddress((void**)&p_w2l, g_wfc2_lo);

    cudaFuncSetAttribute(gemm_mma<0>, cudaFuncAttributeMaxDynamicSharedMemorySize, (int)GEMM_SMEM);
    cudaFuncSetAttribute(gemm_mma<1>, cudaFuncAttributeMaxDynamicSharedMemorySize, (int)GEMM_SMEM);
    cudaFuncSetAttribute(gemm_mma<2>, cudaFuncAttributeMaxDynamicSharedMemorySize, (int)GEMM_SMEM);
    cudaFuncSetAttribute(attn_kernel, cudaFuncAttributeMaxDynamicSharedMemorySize, 4 * 64 * TS * 4);

    dim3 wb(32, 8);
    // 0. transpose+split weights (per-launch; cheap)
    wsplit_kernel<<<dim3(E3 / 32, E / 32), wb>>>(w_attn, p_wqh, p_wql, E, E3);
    wsplit_kernel<<<dim3(E / 32, E / 32), wb>>>(w_proj, p_wph, p_wpl, E, E);
    wsplit_kernel<<<dim3(FF / 32, E / 32), wb>>>(w_fc, p_wfh, p_wfl, E, FF);
    wsplit_kernel<<<dim3(E / 32, FF / 32), wb>>>(w_fc2, p_w2h, p_w2l, FF, E);
    // 1. LN1 -> h (hi/lo)
    ln_kernel<<<ROWS, 256>>>(x, ln1_g, ln1_b, p_hhi, p_hlo);
    // 2. qkv = h @ w_attn + b_attn  [8192 x 2304], K=768
    gemm_mma<0><<<dim3(18, 64), 256, GEMM_SMEM>>>(p_hhi, p_hlo, p_wqh, p_wql,
        b_attn, nullptr, p_qkv, nullptr, nullptr, E3, E);
    // 3. causal flash attention -> attn (hi/lo)
    attn_kernel<<<dim3(16, 96), 128, 4 * 64 * TS * 4>>>();
    // 4. x1 = x + attn @ w_proj + b_proj  [8192 x 768], K=768
    gemm_mma<1><<<dim3(6, 64), 256, GEMM_SMEM>>>(p_ahi, p_alo, p_wph, p_wpl,
        b_proj, x, p_x1, nullptr, nullptr, E, E);
    // 5. LN2 -> h (hi/lo)
    ln_kernel<<<ROWS, 256>>>(p_x1, ln2_g, ln2_b, p_hhi, p_hlo);
    // 6. ff = gelu(h @ w_fc + b_fc) -> hi/lo  [8192 x 3072], K=768
    gemm_mma<2><<<dim3(24, 64), 256, GEMM_SMEM>>>(p_hhi, p_hlo, p_wfh, p_wfl,
        b_fc, nullptr, nullptr, p_fhi, p_flo, FF, E);
    // 7. out = x1 + ff @ w_fc2 + b_fc2  [8192 x 768], K=3072
    gemm_mma<1><<<dim3(6, 64), 256, GEMM_SMEM>>>(p_fhi, p_flo, p_w2h, p_w2l,
        b_fc2, p_x1, out, nullptr, nullptr, E, FF);
}

// round 8
// speedup vs baseline: 2.1801x; 1.0728x over previous
#include <cuda_runtime.h>
#include <cuda_fp16.h>
#include <math.h>
#include <stdint.h>

// Problem dims
constexpr int ROWS = 8 * 1024;   // N*S = 8192
constexpr int E    = 768;
constexpr int E3   = 2304;
constexpr int FF   = 3072;

// ---------------------------------------------------------------------------
// Scratch (device globals: allocation-guard safe)
// ---------------------------------------------------------------------------
__device__ float g_qkv[(size_t)ROWS * E3];
__device__ float g_x1[(size_t)ROWS * E];
__device__ __half g_h[(size_t)ROWS * E];
__device__ __half g_attn[(size_t)ROWS * E];
__device__ __half g_ff[(size_t)ROWS * FF];
// Transposed fp16 weights: [N, K]
__device__ __half g_wqkv[(size_t)E3 * E];
__device__ __half g_wproj[(size_t)E * E];
__device__ __half g_wfc[(size_t)FF * E];
__device__ __half g_wfc2[(size_t)E * FF];

// ---------------------------------------------------------------------------
// Helpers (baseline compute_103 PTX: cp.async + mma.sync + ldmatrix)
// ---------------------------------------------------------------------------
__device__ __forceinline__ uint32_t smem_u32(const void* p) {
    uint32_t a;
    asm("{ .reg .u64 t; cvta.to.shared.u64 t, %1; cvt.u32.u64 %0, t; }" : "=r"(a) : "l"(p));
    return a;
}

#define CP_ASYNC16(dst, src) asm volatile("cp.async.cg.shared.global [%0], [%1], 16;" :: "r"(dst), "l"(src))
#define CP_COMMIT()          asm volatile("cp.async.commit_group;" ::: "memory")
#define CP_WAIT(n)           asm volatile("cp.async.wait_group %0;" :: "n"(n) : "memory")

#define MMA16816F16(d, a0, a1, a2, a3, b0, b1) \
    asm volatile( \
        "mma.sync.aligned.m16n8k16.row.col.f32.f16.f16.f32 " \
        "{%0,%1,%2,%3}, {%4,%5,%6,%7}, {%8,%9}, {%0,%1,%2,%3};" \
        : "+f"((d)[0]), "+f"((d)[1]), "+f"((d)[2]), "+f"((d)[3]) \
        : "r"(a0), "r"(a1), "r"(a2), "r"(a3), "r"(b0), "r"(b1))

#define LDMX4(r0, r1, r2, r3, addr) \
    asm volatile("ldmatrix.sync.aligned.m8n8.x4.shared.b16 {%0,%1,%2,%3}, [%4];" \
        : "=r"(r0), "=r"(r1), "=r"(r2), "=r"(r3) : "r"(addr))

// ---------------------------------------------------------------------------
// LayerNorm -> fp16
// ---------------------------------------------------------------------------
__global__ void __launch_bounds__(256) ln_kernel(const float* __restrict__ x,
                                                 const float* __restrict__ g,
                                                 const float* __restrict__ b,
                                                 __half* __restrict__ out) {
    __shared__ float sh[9];
    int row = blockIdx.x;
    int tid = threadIdx.x;
    const float* xr = x + (size_t)row * E;
    float v0 = xr[tid], v1 = xr[tid + 256], v2 = xr[tid + 512];

    float s = v0 + v1 + v2;
    #pragma unroll
    for (int o = 16; o > 0; o >>= 1) s += __shfl_xor_sync(0xffffffffu, s, o);
    if ((tid & 31) == 0) sh[tid >> 5] = s;
    __syncthreads();
    if (tid == 0) {
        float t = 0.f;
        #pragma unroll
        for (int i = 0; i < 8; i++) t += sh[i];
        sh[8] = t * (1.0f / E);
    }
    __syncthreads();
    float mu = sh[8];
    __syncthreads();

    float d0 = v0 - mu, d1 = v1 - mu, d2 = v2 - mu;
    float s2 = d0 * d0 + d1 * d1 + d2 * d2;
    #pragma unroll
    for (int o = 16; o > 0; o >>= 1) s2 += __shfl_xor_sync(0xffffffffu, s2, o);
    if ((tid & 31) == 0) sh[tid >> 5] = s2;
    __syncthreads();
    if (tid == 0) {
        float t = 0.f;
        #pragma unroll
        for (int i = 0; i < 8; i++) t += sh[i];
        sh[8] = rsqrtf(t * (1.0f / E) + 1e-5f);
    }
    __syncthreads();
    float rs = sh[8];

    size_t rb = (size_t)row * E;
    out[rb + tid]       = __float2half_rn(d0 * rs * g[tid]       + b[tid]);
    out[rb + tid + 256] = __float2half_rn(d1 * rs * g[tid + 256] + b[tid + 256]);
    out[rb + tid + 512] = __float2half_rn(d2 * rs * g[tid + 512] + b[tid + 512]);
}

// ---------------------------------------------------------------------------
// Weight transpose: w[K,N] fp32 -> o[N,K] fp16
// ---------------------------------------------------------------------------
__global__ void __launch_bounds__(256) wsplit_kernel(const float* __restrict__ w,
                                                     __half* __restrict__ o,
                                                     int K, int N) {
    __shared__ float t[32][33];
    int n0 = blockIdx.x * 32, k0 = blockIdx.y * 32;
    int tx = threadIdx.x, ty = threadIdx.y;
    #pragma unroll
    for (int j = 0; j < 32; j += 8)
        t[ty + j][tx] = w[(size_t)(k0 + ty + j) * N + n0 + tx];
    __syncthreads();
    #pragma unroll
    for (int j = 0; j < 32; j += 8)
        o[(size_t)(n0 + ty + j) * K + k0 + tx] = __float2half_rn(t[tx][ty + j]);
}

// ---------------------------------------------------------------------------
// fp16 mma.sync GEMM: C[M,N] = A[M,K] @ B[N,K]^T + bias (+epilogue)
// CTA 128x128, BK=32, 8 warps (4 M x 2 N), warp tile 32x64, single product.
// 3-stage cp.async pipeline, ldmatrix.x4 fragment loads, 80B padded rows.
// MODE 0: fp32 +bias;  MODE 1: fp32 +bias+residual;  MODE 2: +bias, GELU -> fp16
// ---------------------------------------------------------------------------
constexpr int GBK = 32;
constexpr int TILE_B = 128 * 80;               // one subtile: 10240 B (80B rows)
constexpr int STAGE_B = 2 * TILE_B;            // A + B: 20480 B
constexpr size_t GEMM_SMEM = 3 * STAGE_B;      // 61440 B

template <int MODE>
__global__ void __launch_bounds__(256, 2) gemm_mma(
    const __half* __restrict__ A, const __half* __restrict__ B,
    const float* __restrict__ bias, const float* __restrict__ res,
    float* __restrict__ C, __half* __restrict__ Ch,
    int Ndim, int Kdim) {
    extern __shared__ __align__(16) char smem[];
    uint32_t sb = smem_u32(smem);
    int tid = threadIdx.x, wid = tid >> 5, lane = tid & 31;
    int wm = wid & 3, wn = wid >> 2;           // warp grid 4 (M) x 2 (N)
    int m0 = blockIdx.y * 128, n0 = blockIdx.x * 128;
    int r = lane >> 2, c2 = (lane & 3) * 2;
    int lrow = lane & 15, lcol = (lane >> 4) * 16;

    float acc[2][8][4];
    #pragma unroll
    for (int mi = 0; mi < 2; mi++)
        #pragma unroll
        for (int ni = 0; ni < 8; ni++)
            #pragma unroll
            for (int q = 0; q < 4; q++) acc[mi][ni][q] = 0.f;

    // 1024 16B chunks per stage (2 subtiles x 128 rows x 4 chunks), 4/thread
    auto load_stage = [&](int it, int buf) {
        int k0 = it * GBK;
        #pragma unroll
        for (int i = 0; i < 4; i++) {
            int ch = i * 256 + tid;
            int s = ch >> 9, cc = ch & 511;
            int row = cc >> 2, kc = cc & 3;
            uint32_t dst = sb + buf * STAGE_B + s * TILE_B + row * 80 + kc * 16;
            const __half* src = (s ? B + (size_t)(n0 + row) * Kdim
                                   : A + (size_t)(m0 + row) * Kdim) + k0 + kc * 8;
            CP_ASYNC16(dst, src);
        }
        CP_COMMIT();
    };

    load_stage(0, 0);
    load_stage(1, 1);

    int niter = Kdim / GBK;
    for (int it = 0; it < niter; ++it) {
        int buf = it % 3;
        if (it + 1 < niter) CP_WAIT(1); else CP_WAIT(0);
        __syncthreads();
        if (it + 2 < niter) load_stage(it + 2, (it + 2) % 3);

        uint32_t abase = sb + buf * STAGE_B;
        uint32_t bbase = abase + TILE_B;

        #pragma unroll
        for (int ks = 0; ks < 2; ks++) {
            uint32_t ah[2][4];
            #pragma unroll
            for (int mi = 0; mi < 2; mi++) {
                uint32_t addr = abase + (wm * 32 + mi * 16 + lrow) * 80 + ks * 32 + lcol;
                LDMX4(ah[mi][0], ah[mi][1], ah[mi][2], ah[mi][3], addr);
            }
            #pragma unroll
            for (int nb = 0; nb < 4; nb++) {
                uint32_t b0, b1, b2, b3;
                uint32_t addr = bbase + (wn * 64 + nb * 16 + lrow) * 80 + ks * 32 + lcol;
                LDMX4(b0, b1, b2, b3, addr);
                #pragma unroll
                for (int mi = 0; mi < 2; mi++) {
                    MMA16816F16(acc[mi][2 * nb],     ah[mi][0], ah[mi][1], ah[mi][2], ah[mi][3], b0, b2);
                    MMA16816F16(acc[mi][2 * nb + 1], ah[mi][0], ah[mi][1], ah[mi][2], ah[mi][3], b1, b3);
                }
            }
        }
        __syncthreads();
    }

    // Epilogue: direct register writeout, fused bias/residual/GELU
    #pragma unroll
    for (int mi = 0; mi < 2; mi++) {
        #pragma unroll
        for (int ni = 0; ni < 8; ni++) {
            int row = m0 + wm * 32 + mi * 16 + r;
            int col = n0 + wn * 64 + ni * 8 + c2;
            float2 bv = *(const float2*)&bias[col];
            #pragma unroll
            for (int half_i = 0; half_i < 2; half_i++) {
                int rr = row + half_i * 8;
                float v0 = acc[mi][ni][half_i * 2 + 0] + bv.x;
                float v1 = acc[mi][ni][half_i * 2 + 1] + bv.y;
                size_t gi = (size_t)rr * Ndim + col;
                if (MODE == 2) {
                    v0 = 0.5f * v0 * (1.0f + erff(v0 * 0.70710678118f));
                    v1 = 0.5f * v1 * (1.0f + erff(v1 * 0.70710678118f));
                    *(__half2*)&Ch[gi] = __floats2half2_rn(v0, v1);
                } else {
                    if (MODE == 1) {
                        float2 rv = *(const float2*)&res[gi];
                        v0 += rv.x; v1 += rv.y;
                    }
                    *(float2*)&C[gi] = make_float2(v0, v1);
                }
            }
        }
    }
}

// ---------------------------------------------------------------------------
// Flash attention (SIMT fp32), outputs fp16
// ---------------------------------------------------------------------------
constexpr int TS = 65;

__global__ void __launch_bounds__(128) attn_kernel() {
    extern __shared__ float sm[];
    float* Qs = sm;
    float* Ks = Qs + 64 * TS;
    float* Vs = Ks + 64 * TS;
    float* Ps = Vs + 64 * TS;

    int qt = blockIdx.x;
    int nh = blockIdx.y;
    int h = nh % 12, n = nh / 12;
    int row0 = n * 1024 + qt * 64;
    int tid = threadIdx.x;
    int cq = tid & 3, r = tid >> 2;
    int hoff = h * 64;

    for (int i = tid; i < 64 * 16; i += 128) {
        int rr = i >> 4, c4 = (i & 15) << 2;
        float4 v = *(const float4*)&g_qkv[(size_t)(row0 + rr) * 2304 + hoff + c4];
        float* dst = &Qs[rr * TS + c4];
        dst[0] = v.x; dst[1] = v.y; dst[2] = v.z; dst[3] = v.w;
    }

    float m0v = -1e30f, m1v = -1e30f, l0 = 0.f, l1 = 0.f;
    float o0[16], o1[16];
    #pragma unroll
    for (int i = 0; i < 16; i++) { o0[i] = 0.f; o1[i] = 0.f; }

    for (int t = 0; t <= qt; ++t) {
        int krow0 = n * 1024 + t * 64;
        for (int i = tid; i < 64 * 16; i += 128) {
            int rr = i >> 4, c4 = (i & 15) << 2;
            size_t base = (size_t)(krow0 + rr) * 2304 + hoff + c4;
            float4 kv = *(const float4*)&g_qkv[base + 768];
            float* dk = &Ks[rr * TS + c4];
            dk[0] = kv.x; dk[1] = kv.y; dk[2] = kv.z; dk[3] = kv.w;
            float4 vv = *(const float4*)&g_qkv[base + 1536];
            float* dv = &Vs[rr * TS + c4];
            dv[0] = vv.x; dv[1] = vv.y; dv[2] = vv.z; dv[3] = vv.w;
        }
        __syncthreads();

        float s0[16], s1[16];
        #pragma unroll
        for (int j = 0; j < 16; j++) { s0[j] = 0.f; s1[j] = 0.f; }
        #pragma unroll 4
        for (int d = 0; d < 64; ++d) {
            float q0 = Qs[r * TS + d];
            float q1 = Qs[(r + 32) * TS + d];
            #pragma unroll
            for (int j = 0; j < 16; j++) {
                float kv = Ks[(cq + 4 * j) * TS + d];
                s0[j] += q0 * kv;
                s1[j] += q1 * kv;
            }
        }

        bool diag = (t == qt);
        #pragma unroll
        for (int j = 0; j < 16; j++) {
            int col = cq + 4 * j;
            s0[j] = (diag && col > r)      ? -1e30f : s0[j] * 0.125f;
            s1[j] = (diag && col > r + 32) ? -1e30f : s1[j] * 0.125f;
        }

        float mx0 = -1e30f, mx1 = -1e30f;
        #pragma unroll
        for (int j = 0; j < 16; j++) {
            mx0 = fmaxf(mx0, s0[j]);
            mx1 = fmaxf(mx1, s1[j]);
        }
        mx0 = fmaxf(mx0, __shfl_xor_sync(0xffffffffu, mx0, 1));
        mx0 = fmaxf(mx0, __shfl_xor_sync(0xffffffffu, mx0, 2));
        mx1 = fmaxf(mx1, __shfl_xor_sync(0xffffffffu, mx1, 1));
        mx1 = fmaxf(mx1, __shfl_xor_sync(0xffffffffu, mx1, 2));

        float nm0 = fmaxf(m0v, mx0), nm1 = fmaxf(m1v, mx1);
        float f0 = __expf(m0v - nm0), f1 = __expf(m1v - nm1);
        float ls0 = 0.f, ls1 = 0.f;
        #pragma unroll
        for (int j = 0; j < 16; j++) {
            float p0 = __expf(s0[j] - nm0); s0[j] = p0; ls0 += p0;
            float p1 = __expf(s1[j] - nm1); s1[j] = p1; ls1 += p1;
        }
        ls0 += __shfl_xor_sync(0xffffffffu, ls0, 1);
        ls0 += __shfl_xor_sync(0xffffffffu, ls0, 2);
        ls1 += __shfl_xor_sync(0xffffffffu, ls1, 1);
        ls1 += __shfl_xor_sync(0xffffffffu, ls1, 2);
        l0 = l0 * f0 + ls0;
        l1 = l1 * f1 + ls1;
        m0v = nm0; m1v = nm1;
        #pragma unroll
        for (int i = 0; i < 16; i++) { o0[i] *= f0; o1[i] *= f1; }

        #pragma unroll
        for (int j = 0; j < 16; j++) {
            Ps[r * TS + cq + 4 * j] = s0[j];
            Ps[(r + 32) * TS + cq + 4 * j] = s1[j];
        }
        __syncthreads();

        #pragma unroll 4
        for (int j = 0; j < 64; ++j) {
            float p0 = Ps[r * TS + j];
            float p1 = Ps[(r + 32) * TS + j];
            #pragma unroll
            for (int i = 0; i < 16; i++) {
                float vv = Vs[j * TS + cq + 4 * i];
                o0[i] += p0 * vv;
                o1[i] += p1 * vv;
            }
        }
        __syncthreads();
    }

    float inv0 = 1.f / l0, inv1 = 1.f / l1;
    size_t ob0 = (size_t)(row0 + r) * 768 + hoff + cq;
    size_t ob1 = (size_t)(row0 + r + 32) * 768 + hoff + cq;
    #pragma unroll
    for (int i = 0; i < 16; i++) {
        g_attn[ob0 + 4 * i] = __float2half_rn(o0[i] * inv0);
        g_attn[ob1 + 4 * i] = __float2half_rn(o1[i] * inv1);
    }
}

// ---------------------------------------------------------------------------
extern "C" void kernel_launch(void* const* d_in, const int* in_sizes, int n_in,
                              void* d_out, int out_size) {
    const float* x      = (const float*)d_in[0];
    const float* ln1_g  = (const float*)d_in[1];
    const float* ln1_b  = (const float*)d_in[2];
    const float* ln2_g  = (const float*)d_in[3];
    const float* ln2_b  = (const float*)d_in[4];
    const float* w_attn = (const float*)d_in[5];
    const float* b_attn = (const float*)d_in[6];
    const float* w_proj = (const float*)d_in[7];
    const float* b_proj = (const float*)d_in[8];
    const float* w_fc   = (const float*)d_in[9];
    const float* b_fc   = (const float*)d_in[10];
    const float* w_fc2  = (const float*)d_in[11];
    const float* b_fc2  = (const float*)d_in[12];
    float* out = (float*)d_out;

    float *p_qkv, *p_x1;
    __half *p_h, *p_attn, *p_ff, *p_wq, *p_wp, *p_wf, *p_w2;
    cudaGetSymbolAddress((void**)&p_qkv, g_qkv);
    cudaGetSymbolAddress((void**)&p_x1, g_x1);
    cudaGetSymbolAddress((void**)&p_h, g_h);
    cudaGetSymbolAddress((void**)&p_attn, g_attn);
    cudaGetSymbolAddress((void**)&p_ff, g_ff);
    cudaGetSymbolAddress((void**)&p_wq, g_wqkv);
    cudaGetSymbolAddress((void**)&p_wp, g_wproj);
    cudaGetSymbolAddress((void**)&p_wf, g_wfc);
    cudaGetSymbolAddress((void**)&p_w2, g_wfc2);

    cudaFuncSetAttribute(gemm_mma<0>, cudaFuncAttributeMaxDynamicSharedMemorySize, (int)GEMM_SMEM);
    cudaFuncSetAttribute(gemm_mma<1>, cudaFuncAttributeMaxDynamicSharedMemorySize, (int)GEMM_SMEM);
    cudaFuncSetAttribute(gemm_mma<2>, cudaFuncAttributeMaxDynamicSharedMemorySize, (int)GEMM_SMEM);
    cudaFuncSetAttribute(attn_kernel, cudaFuncAttributeMaxDynamicSharedMemorySize, 4 * 64 * TS * 4);

    dim3 wb(32, 8);
    // 0. transpose weights to fp16 [N,K] (per-launch; cheap)
    wsplit_kernel<<<dim3(E3 / 32, E / 32), wb>>>(w_attn, p_wq, E, E3);
    wsplit_kernel<<<dim3(E / 32, E / 32), wb>>>(w_proj, p_wp, E, E);
    wsplit_kernel<<<dim3(FF / 32, E / 32), wb>>>(w_fc, p_wf, E, FF);
    wsplit_kernel<<<dim3(E / 32, FF / 32), wb>>>(w_fc2, p_w2, FF, E);
    // 1. LN1 -> h (fp16)
    ln_kernel<<<ROWS, 256>>>(x, ln1_g, ln1_b, p_h);
    // 2. qkv = h @ w_attn + b_attn  [8192 x 2304], K=768
    gemm_mma<0><<<dim3(18, 64), 256, GEMM_SMEM>>>(p_h, p_wq, b_attn, nullptr,
                                                  p_qkv, nullptr, E3, E);
    // 3. causal flash attention -> attn (fp16)
    attn_kernel<<<dim3(16, 96), 128, 4 * 64 * TS * 4>>>();
    // 4. x1 = x + attn @ w_proj + b_proj  [8192 x 768], K=768
    gemm_mma<1><<<dim3(6, 64), 256, GEMM_SMEM>>>(p_attn, p_wp, b_proj, x,
                                                 p_x1, nullptr, E, E);
    // 5. LN2 -> h (fp16)
    ln_kernel<<<ROWS, 256>>>(p_x1, ln2_g, ln2_b, p_h);
    // 6. ff = gelu(h @ w_fc + b_fc) -> fp16  [8192 x 3072], K=768
    gemm_mma<2><<<dim3(24, 64), 256, GEMM_SMEM>>>(p_h, p_wf, b_fc, nullptr,
                                                  nullptr, p_ff, FF, E);
    // 7. out = x1 + ff @ w_fc2 + b_fc2  [8192 x 768], K=3072
    gemm_mma<1><<<dim3(6, 64), 256, GEMM_SMEM>>>(p_ff, p_w2, b_fc2, p_x1,
                                                 out, nullptr, E, FF);
}

// round 10
// speedup vs baseline: 6.4392x; 2.9536x over previous
#include <cuda_runtime.h>
#include <cuda_fp16.h>
#include <math.h>
#include <stdint.h>

// Problem dims
constexpr int ROWS = 8 * 1024;   // N*S = 8192
constexpr int E    = 768;
constexpr int E3   = 2304;
constexpr int FF   = 3072;

// ---------------------------------------------------------------------------
// Scratch (device globals: allocation-guard safe)
// ---------------------------------------------------------------------------
__device__ float g_x1[(size_t)ROWS * E];
__device__ __half g_h[(size_t)ROWS * E];
__device__ __half g_attn[(size_t)ROWS * E];
__device__ __half g_ff[(size_t)ROWS * FF];
// Per-head QKV: [n(8)][h(12)][s(1024)][d(64)] fp16; Q pre-scaled by 0.125
__device__ __half g_q[(size_t)ROWS * E];
__device__ __half g_k[(size_t)ROWS * E];
__device__ __half g_v[(size_t)ROWS * E];
// Transposed fp16 weights: [N, K]
__device__ __half g_wqkv[(size_t)E3 * E];
__device__ __half g_wproj[(size_t)E * E];
__device__ __half g_wfc[(size_t)FF * E];
__device__ __half g_wfc2[(size_t)E * FF];

// ---------------------------------------------------------------------------
// Helpers (baseline compute_103 PTX: cp.async + mma.sync + ldmatrix)
// ---------------------------------------------------------------------------
__device__ __forceinline__ uint32_t smem_u32(const void* p) {
    uint32_t a;
    asm("{ .reg .u64 t; cvta.to.shared.u64 t, %1; cvt.u32.u64 %0, t; }" : "=r"(a) : "l"(p));
    return a;
}

#define CP_ASYNC16(dst, src) asm volatile("cp.async.cg.shared.global [%0], [%1], 16;" :: "r"(dst), "l"(src))
#define CP_COMMIT()          asm volatile("cp.async.commit_group;" ::: "memory")
#define CP_WAIT(n)           asm volatile("cp.async.wait_group %0;" :: "n"(n) : "memory")

#define MMA16816F16(d, a0, a1, a2, a3, b0, b1) \
    asm volatile( \
        "mma.sync.aligned.m16n8k16.row.col.f32.f16.f16.f32 " \
        "{%0,%1,%2,%3}, {%4,%5,%6,%7}, {%8,%9}, {%0,%1,%2,%3};" \
        : "+f"((d)[0]), "+f"((d)[1]), "+f"((d)[2]), "+f"((d)[3]) \
        : "r"(a0), "r"(a1), "r"(a2), "r"(a3), "r"(b0), "r"(b1))

#define LDMX4(r0, r1, r2, r3, addr) \
    asm volatile("ldmatrix.sync.aligned.m8n8.x4.shared.b16 {%0,%1,%2,%3}, [%4];" \
        : "=r"(r0), "=r"(r1), "=r"(r2), "=r"(r3) : "r"(addr))

#define LDMX4T(r0, r1, r2, r3, addr) \
    asm volatile("ldmatrix.sync.aligned.m8n8.x4.trans.shared.b16 {%0,%1,%2,%3}, [%4];" \
        : "=r"(r0), "=r"(r1), "=r"(r2), "=r"(r3) : "r"(addr))

__device__ __forceinline__ uint32_t packh2(float a, float b) {
    __half2 h = __floats2half2_rn(a, b);
    return *(uint32_t*)&h;
}

// ---------------------------------------------------------------------------
// LayerNorm -> fp16
// ---------------------------------------------------------------------------
__global__ void __launch_bounds__(256) ln_kernel(const float* __restrict__ x,
                                                 const float* __restrict__ g,
                                                 const float* __restrict__ b,
                                                 __half* __restrict__ out) {
    __shared__ float sh[9];
    int row = blockIdx.x;
    int tid = threadIdx.x;
    const float* xr = x + (size_t)row * E;
    float v0 = xr[tid], v1 = xr[tid + 256], v2 = xr[tid + 512];

    float s = v0 + v1 + v2;
    #pragma unroll
    for (int o = 16; o > 0; o >>= 1) s += __shfl_xor_sync(0xffffffffu, s, o);
    if ((tid & 31) == 0) sh[tid >> 5] = s;
    __syncthreads();
    if (tid == 0) {
        float t = 0.f;
        #pragma unroll
        for (int i = 0; i < 8; i++) t += sh[i];
        sh[8] = t * (1.0f / E);
    }
    __syncthreads();
    float mu = sh[8];
    __syncthreads();

    float d0 = v0 - mu, d1 = v1 - mu, d2 = v2 - mu;
    float s2 = d0 * d0 + d1 * d1 + d2 * d2;
    #pragma unroll
    for (int o = 16; o > 0; o >>= 1) s2 += __shfl_xor_sync(0xffffffffu, s2, o);
    if ((tid & 31) == 0) sh[tid >> 5] = s2;
    __syncthreads();
    if (tid == 0) {
        float t = 0.f;
        #pragma unroll
        for (int i = 0; i < 8; i++) t += sh[i];
        sh[8] = rsqrtf(t * (1.0f / E) + 1e-5f);
    }
    __syncthreads();
    float rs = sh[8];

    size_t rb = (size_t)row * E;
    out[rb + tid]       = __float2half_rn(d0 * rs * g[tid]       + b[tid]);
    out[rb + tid + 256] = __float2half_rn(d1 * rs * g[tid + 256] + b[tid + 256]);
    out[rb + tid + 512] = __float2half_rn(d2 * rs * g[tid + 512] + b[tid + 512]);
}

// ---------------------------------------------------------------------------
// Weight transpose: w[K,N] fp32 -> o[N,K] fp16
// ---------------------------------------------------------------------------
__global__ void __launch_bounds__(256) wsplit_kernel(const float* __restrict__ w,
                                                     __half* __restrict__ o,
                                                     int K, int N) {
    __shared__ float t[32][33];
    int n0 = blockIdx.x * 32, k0 = blockIdx.y * 32;
    int tx = threadIdx.x, ty = threadIdx.y;
    #pragma unroll
    for (int j = 0; j < 32; j += 8)
        t[ty + j][tx] = w[(size_t)(k0 + ty + j) * N + n0 + tx];
    __syncthreads();
    #pragma unroll
    for (int j = 0; j < 32; j += 8)
        o[(size_t)(n0 + ty + j) * K + k0 + tx] = __float2half_rn(t[tx][ty + j]);
}

// ---------------------------------------------------------------------------
// fp16 mma.sync GEMM: C[M,N] = A[M,K] @ B[N,K]^T + bias (+epilogue)
// CTA 128x128, BK=32, 8 warps (4 M x 2 N), warp tile 32x64.
// 4-stage cp.async pipeline, ldmatrix.x4 fragment loads, 80B padded rows.
// MODE 1: fp32 +bias+residual;  MODE 2: +bias, GELU -> fp16
// MODE 3: fp16 qkv scatter to per-head q/k/v (q scaled by 0.125)
// ---------------------------------------------------------------------------
constexpr int GBK = 32;
constexpr int TILE_B = 128 * 80;               // one subtile: 10240 B (80B rows)
constexpr int STAGE_B = 2 * TILE_B;            // A + B: 20480 B
constexpr int NSTAGE = 4;
constexpr size_t GEMM_SMEM = NSTAGE * STAGE_B; // 81920 B

template <int MODE>
__global__ void __launch_bounds__(256, 2) gemm_mma(
    const __half* __restrict__ A, const __half* __restrict__ B,
    const float* __restrict__ bias, const float* __restrict__ res,
    float* __restrict__ C, __half* __restrict__ Ch,
    __half* __restrict__ Qo, __half* __restrict__ Ko, __half* __restrict__ Vo,
    int Ndim, int Kdim) {
    extern __shared__ __align__(16) char smem[];
    uint32_t sb = smem_u32(smem);
    int tid = threadIdx.x, wid = tid >> 5, lane = tid & 31;
    int wm = wid & 3, wn = wid >> 2;           // warp grid 4 (M) x 2 (N)
    int m0 = blockIdx.y * 128, n0 = blockIdx.x * 128;
    int r = lane >> 2, c2 = (lane & 3) * 2;
    int lrow = lane & 15, lcol = (lane >> 4) * 16;

    float acc[2][8][4];
    #pragma unroll
    for (int mi = 0; mi < 2; mi++)
        #pragma unroll
        for (int ni = 0; ni < 8; ni++)
            #pragma unroll
            for (int q = 0; q < 4; q++) acc[mi][ni][q] = 0.f;

    auto load_stage = [&](int it, int buf) {
        int k0 = it * GBK;
        #pragma unroll
        for (int i = 0; i < 4; i++) {
            int ch = i * 256 + tid;
            int s = ch >> 9, cc = ch & 511;
            int row = cc >> 2, kc = cc & 3;
            uint32_t dst = sb + buf * STAGE_B + s * TILE_B + row * 80 + kc * 16;
            const __half* src = (s ? B + (size_t)(n0 + row) * Kdim
                                   : A + (size_t)(m0 + row) * Kdim) + k0 + kc * 8;
            CP_ASYNC16(dst, src);
        }
        CP_COMMIT();
    };

    load_stage(0, 0);
    load_stage(1, 1);
    load_stage(2, 2);

    int niter = Kdim / GBK;
    for (int it = 0; it < niter; ++it) {
        int buf = it % NSTAGE;
        if (it + 2 < niter) CP_WAIT(2);
        else if (it + 1 < niter) CP_WAIT(1);
        else CP_WAIT(0);
        __syncthreads();
        if (it + 3 < niter) load_stage(it + 3, (it + 3) % NSTAGE);

        uint32_t abase = sb + buf * STAGE_B;
        uint32_t bbase = abase + TILE_B;

        #pragma unroll
        for (int ks = 0; ks < 2; ks++) {
            uint32_t ah[2][4];
            #pragma unroll
            for (int mi = 0; mi < 2; mi++) {
                uint32_t addr = abase + (wm * 32 + mi * 16 + lrow) * 80 + ks * 32 + lcol;
                LDMX4(ah[mi][0], ah[mi][1], ah[mi][2], ah[mi][3], addr);
            }
            #pragma unroll
            for (int nb = 0; nb < 4; nb++) {
                uint32_t b0, b1, b2, b3;
                uint32_t addr = bbase + (wn * 64 + nb * 16 + lrow) * 80 + ks * 32 + lcol;
                LDMX4(b0, b1, b2, b3, addr);
                #pragma unroll
                for (int mi = 0; mi < 2; mi++) {
                    MMA16816F16(acc[mi][2 * nb],     ah[mi][0], ah[mi][1], ah[mi][2], ah[mi][3], b0, b2);
                    MMA16816F16(acc[mi][2 * nb + 1], ah[mi][0], ah[mi][1], ah[mi][2], ah[mi][3], b1, b3);
                }
            }
        }
        __syncthreads();
    }

    // Epilogue: direct register writeout
    #pragma unroll
    for (int mi = 0; mi < 2; mi++) {
        #pragma unroll
        for (int ni = 0; ni < 8; ni++) {
            int row = m0 + wm * 32 + mi * 16 + r;
            int col = n0 + wn * 64 + ni * 8 + c2;
            float2 bv = *(const float2*)&bias[col];
            #pragma unroll
            for (int hf = 0; hf < 2; hf++) {
                int rr = row + hf * 8;
                float v0 = acc[mi][ni][hf * 2 + 0] + bv.x;
                float v1 = acc[mi][ni][hf * 2 + 1] + bv.y;
                if (MODE == 3) {
                    int which = col / 768;
                    int h = (col % 768) >> 6;
                    int d = col & 63;
                    size_t dst = ((size_t)((rr >> 10) * 12 + h) * 1024 + (rr & 1023)) * 64 + d;
                    __half* base = (which == 0) ? Qo : (which == 1) ? Ko : Vo;
                    float sc = (which == 0) ? 0.125f : 1.0f;
                    *(__half2*)&base[dst] = __floats2half2_rn(v0 * sc, v1 * sc);
                } else {
                    size_t gi = (size_t)rr * Ndim + col;
                    if (MODE == 2) {
                        v0 = 0.5f * v0 * (1.0f + erff(v0 * 0.70710678118f));
                        v1 = 0.5f * v1 * (1.0f + erff(v1 * 0.70710678118f));
                        *(__half2*)&Ch[gi] = __floats2half2_rn(v0, v1);
                    } else {
                        float2 rv = *(const float2*)&res[gi];
                        v0 += rv.x; v1 += rv.y;
                        *(float2*)&C[gi] = make_float2(v0, v1);
                    }
                }
            }
        }
    }
}

// ---------------------------------------------------------------------------
// Tensor-core flash attention (fp16 mma, FA2-style).
// Grid (16 q-tiles, 96 n*h), 128 threads = 4 warps; warp w owns q-rows
// [w*16, w*16+16). KV tiles of 64, double-buffered cp.async.
// Q pre-scaled by 0.125; online softmax in fp32; P reused as fp16 A-frags.
// ---------------------------------------------------------------------------
constexpr int AQS = 72;                         // padded row stride (halves) = 144B
constexpr int ATT_TILE_B = 64 * AQS * 2;        // 9216 B
constexpr size_t ATT_SMEM = 5 * ATT_TILE_B;     // Q + 2*K + 2*V = 46080 B

__global__ void __launch_bounds__(128) attn_kernel() {
    extern __shared__ __align__(16) char smem[];
    uint32_t sb = smem_u32(smem);
    uint32_t Qb = sb;
    uint32_t Kb[2] = {sb + ATT_TILE_B, sb + 2 * ATT_TILE_B};
    uint32_t Vb[2] = {sb + 3 * ATT_TILE_B, sb + 4 * ATT_TILE_B};

    int qt = blockIdx.x;
    int nh = blockIdx.y;                        // n*12 + h
    size_t hbase = (size_t)nh * 1024 * 64;      // head base in g_q/g_k/g_v
    int n = nh / 12, h = nh % 12;
    int tid = threadIdx.x, wid = tid >> 5, lane = tid & 31;
    int r = lane >> 2, c2 = (lane & 3) * 2;
    int lrow = lane & 15, lcol = (lane >> 4) * 16;  // 16B units

    // tile loader: 64 rows x 128B, 512 chunks, 4/thread
    auto load_tile = [&](const __half* g, int t0, uint32_t dstb) {
        #pragma unroll
        for (int i = 0; i < 4; i++) {
            int ch = i * 128 + tid;
            int row = ch >> 3, kc = ch & 7;
            CP_ASYNC16(dstb + row * (AQS * 2) + kc * 16,
                       g + hbase + (size_t)(t0 + row) * 64 + kc * 8);
        }
        CP_COMMIT();
    };

    // Preload Q and first KV tile
    load_tile(g_q, qt * 64, Qb);
    load_tile(g_k, 0, Kb[0]);
    load_tile(g_v, 0, Vb[0]);
    CP_WAIT(0);
    __syncthreads();

    // Q fragments live in registers for the whole kernel: 4 k16-blocks
    uint32_t qf[4][4];
    #pragma unroll
    for (int kb = 0; kb < 4; kb++) {
        uint32_t addr = Qb + (wid * 16 + lrow) * (AQS * 2) + kb * 32 + lcol;
        LDMX4(qf[kb][0], qf[kb][1], qf[kb][2], qf[kb][3], addr);
    }

    float m0v = -1e30f, m1v = -1e30f, l0 = 0.f, l1 = 0.f;
    float o[8][4];
    #pragma unroll
    for (int db = 0; db < 8; db++)
        #pragma unroll
        for (int q = 0; q < 4; q++) o[db][q] = 0.f;

    for (int t = 0; t <= qt; ++t) {
        int buf = t & 1;
        if (t < qt) {
            load_tile(g_k, (t + 1) * 64, Kb[buf ^ 1]);
            load_tile(g_v, (t + 1) * 64, Vb[buf ^ 1]);
        }

        // S = Q @ K^T  (16 x 64 per warp)
        float s[8][4];
        #pragma unroll
        for (int nb = 0; nb < 8; nb++)
            #pragma unroll
            for (int q = 0; q < 4; q++) s[nb][q] = 0.f;
        #pragma unroll
        for (int kb = 0; kb < 4; kb++) {
            #pragma unroll
            for (int nb16 = 0; nb16 < 4; nb16++) {
                uint32_t b0, b1, b2, b3;
                uint32_t addr = Kb[buf] + (nb16 * 16 + lrow) * (AQS * 2) + kb * 32 + lcol;
                LDMX4(b0, b1, b2, b3, addr);
                MMA16816F16(s[nb16 * 2],     qf[kb][0], qf[kb][1], qf[kb][2], qf[kb][3], b0, b2);
                MMA16816F16(s[nb16 * 2 + 1], qf[kb][0], qf[kb][1], qf[kb][2], qf[kb][3], b1, b3);
            }
        }

        // Causal mask on diagonal tile
        if (t == qt) {
            int row0 = qt * 64 + wid * 16 + r;
            #pragma unroll
            for (int nb = 0; nb < 8; nb++) {
                int col = t * 64 + nb * 8 + c2;
                if (col > row0)     s[nb][0] = -1e30f;
                if (col + 1 > row0) s[nb][1] = -1e30f;
                if (col > row0 + 8)     s[nb][2] = -1e30f;
                if (col + 1 > row0 + 8) s[nb][3] = -1e30f;
            }
        }

        // Online softmax (rows r and r+8 of this warp's 16)
        float mx0 = -1e30f, mx1 = -1e30f;
        #pragma unroll
        for (int nb = 0; nb < 8; nb++) {
            mx0 = fmaxf(mx0, fmaxf(s[nb][0], s[nb][1]));
            mx1 = fmaxf(mx1, fmaxf(s[nb][2], s[nb][3]));
        }
        mx0 = fmaxf(mx0, __shfl_xor_sync(0xffffffffu, mx0, 1));
        mx0 = fmaxf(mx0, __shfl_xor_sync(0xffffffffu, mx0, 2));
        mx1 = fmaxf(mx1, __shfl_xor_sync(0xffffffffu, mx1, 1));
        mx1 = fmaxf(mx1, __shfl_xor_sync(0xffffffffu, mx1, 2));

        float nm0 = fmaxf(m0v, mx0), nm1 = fmaxf(m1v, mx1);
        float f0 = __expf(m0v - nm0), f1 = __expf(m1v - nm1);
        float ls0 = 0.f, ls1 = 0.f;
        #pragma unroll
        for (int nb = 0; nb < 8; nb++) {
            s[nb][0] = __expf(s[nb][0] - nm0); ls0 += s[nb][0];
            s[nb][1] = __expf(s[nb][1] - nm0); ls0 += s[nb][1];
            s[nb][2] = __expf(s[nb][2] - nm1); ls1 += s[nb][2];
            s[nb][3] = __expf(s[nb][3] - nm1); ls1 += s[nb][3];
        }
        l0 = l0 * f0 + ls0;      // per-lane partial; quad-reduced at end
        l1 = l1 * f1 + ls1;
        m0v = nm0; m1v = nm1;
        #pragma unroll
        for (int db = 0; db < 8; db++) {
            o[db][0] *= f0; o[db][1] *= f0;
            o[db][2] *= f1; o[db][3] *= f1;
        }

        // O += P @ V  (P fp16 from registers)
        #pragma unroll
        for (int kb2 = 0; kb2 < 4; kb2++) {
            uint32_t a0 = packh2(s[2 * kb2][0],     s[2 * kb2][1]);
            uint32_t a1 = packh2(s[2 * kb2][2],     s[2 * kb2][3]);
            uint32_t a2 = packh2(s[2 * kb2 + 1][0], s[2 * kb2 + 1][1]);
            uint32_t a3 = packh2(s[2 * kb2 + 1][2], s[2 * kb2 + 1][3]);
            #pragma unroll
            for (int db2 = 0; db2 < 4; db2++) {
                uint32_t v0, v1, v2, v3;
                uint32_t addr = Vb[buf] + (kb2 * 16 + lrow) * (AQS * 2) + db2 * 32 + lcol;
                LDMX4T(v0, v1, v2, v3, addr);
                MMA16816F16(o[db2 * 2],     a0, a1, a2, a3, v0, v1);
                MMA16816F16(o[db2 * 2 + 1], a0, a1, a2, a3, v2, v3);
            }
        }

        if (t < qt) {
            CP_WAIT(0);
            __syncthreads();
        }
    }

    // Reduce l over the quad, normalize, write fp16 [rows, E]
    l0 += __shfl_xor_sync(0xffffffffu, l0, 1);
    l0 += __shfl_xor_sync(0xffffffffu, l0, 2);
    l1 += __shfl_xor_sync(0xffffffffu, l1, 1);
    l1 += __shfl_xor_sync(0xffffffffu, l1, 2);
    float inv0 = 1.f / l0, inv1 = 1.f / l1;

    int row0 = n * 1024 + qt * 64 + wid * 16 + r;
    int colb = h * 64;
    #pragma unroll
    for (int db = 0; db < 8; db++) {
        size_t gi0 = (size_t)row0 * 768 + colb + db * 8 + c2;
        size_t gi1 = (size_t)(row0 + 8) * 768 + colb + db * 8 + c2;
        *(__half2*)&g_attn[gi0] = __floats2half2_rn(o[db][0] * inv0, o[db][1] * inv0);
        *(__half2*)&g_attn[gi1] = __floats2half2_rn(o[db][2] * inv1, o[db][3] * inv1);
    }
}

// ---------------------------------------------------------------------------
extern "C" void kernel_launch(void* const* d_in, const int* in_sizes, int n_in,
                              void* d_out, int out_size) {
    const float* x      = (const float*)d_in[0];
    const float* ln1_g  = (const float*)d_in[1];
    const float* ln1_b  = (const float*)d_in[2];
    const float* ln2_g  = (const float*)d_in[3];
    const float* ln2_b  = (const float*)d_in[4];
    const float* w_attn = (const float*)d_in[5];
    const float* b_attn = (const float*)d_in[6];
    const float* w_proj = (const float*)d_in[7];
    const float* b_proj = (const float*)d_in[8];
    const float* w_fc   = (const float*)d_in[9];
    const float* b_fc   = (const float*)d_in[10];
    const float* w_fc2  = (const float*)d_in[11];
    const float* b_fc2  = (const float*)d_in[12];
    float* out = (float*)d_out;

    float* p_x1;
    __half *p_h, *p_attn, *p_ff, *p_q, *p_k, *p_v;
    __half *p_wq, *p_wp, *p_wf, *p_w2;
    cudaGetSymbolAddress((void**)&p_x1, g_x1);
    cudaGetSymbolAddress((void**)&p_h, g_h);
    cudaGetSymbolAddress((void**)&p_attn, g_attn);
    cudaGetSymbolAddress((void**)&p_ff, g_ff);
    cudaGetSymbolAddress((void**)&p_q, g_q);
    cudaGetSymbolAddress((void**)&p_k, g_k);
    cudaGetSymbolAddress((void**)&p_v, g_v);
    cudaGetSymbolAddress((void**)&p_wq, g_wqkv);
    cudaGetSymbolAddress((void**)&p_wp, g_wproj);
    cudaGetSymbolAddress((void**)&p_wf, g_wfc);
    cudaGetSymbolAddress((void**)&p_w2, g_wfc2);

    cudaFuncSetAttribute(gemm_mma<1>, cudaFuncAttributeMaxDynamicSharedMemorySize, (int)GEMM_SMEM);
    cudaFuncSetAttribute(gemm_mma<2>, cudaFuncAttributeMaxDynamicSharedMemorySize, (int)GEMM_SMEM);
    cudaFuncSetAttribute(gemm_mma<3>, cudaFuncAttributeMaxDynamicSharedMemorySize, (int)GEMM_SMEM);
    cudaFuncSetAttribute(attn_kernel, cudaFuncAttributeMaxDynamicSharedMemorySize, (int)ATT_SMEM);

    dim3 wb(32, 8);
    // 0. transpose weights to fp16 [N,K]
    wsplit_kernel<<<dim3(E3 / 32, E / 32), wb>>>(w_attn, p_wq, E, E3);
    wsplit_kernel<<<dim3(E / 32, E / 32), wb>>>(w_proj, p_wp, E, E);
    wsplit_kernel<<<dim3(FF / 32, E / 32), wb>>>(w_fc, p_wf, E, FF);
    wsplit_kernel<<<dim3(E / 32, FF / 32), wb>>>(w_fc2, p_w2, FF, E);
    // 1. LN1 -> h (fp16)
    ln_kernel<<<ROWS, 256>>>(x, ln1_g, ln1_b, p_h);
    // 2. qkv GEMM -> per-head q/k/v fp16 (q scaled by 0.125)
    gemm_mma<3><<<dim3(18, 64), 256, GEMM_SMEM>>>(p_h, p_wq, b_attn, nullptr,
        nullptr, nullptr, p_q, p_k, p_v, E3, E);
    // 3. tensor-core causal flash attention -> attn (fp16 [rows, E])
    attn_kernel<<<dim3(16, 96), 128, ATT_SMEM>>>();
    // 4. x1 = x + attn @ w_proj + b_proj
    gemm_mma<1><<<dim3(6, 64), 256, GEMM_SMEM>>>(p_attn, p_wp, b_proj, x,
        p_x1, nullptr, nullptr, nullptr, nullptr, E, E);
    // 5. LN2 -> h (fp16)
    ln_kernel<<<ROWS, 256>>>(p_x1, ln2_g, ln2_b, p_h);
    // 6. ff = gelu(h @ w_fc + b_fc) -> fp16
    gemm_mma<2><<<dim3(24, 64), 256, GEMM_SMEM>>>(p_h, p_wf, b_fc, nullptr,
        nullptr, p_ff, nullptr, nullptr, nullptr, FF, E);
    // 7. out = x1 + ff @ w_fc2 + b_fc2
    gemm_mma<1><<<dim3(6, 64), 256, GEMM_SMEM>>>(p_ff, p_w2, b_fc2, p_x1,
        out, nullptr, nullptr, nullptr, nullptr, E, FF);
}

// round 11
// speedup vs baseline: 6.6046x; 1.0257x over previous
#include <cuda_runtime.h>
#include <cuda_fp16.h>
#include <math.h>
#include <stdint.h>

// Problem dims
constexpr int ROWS = 8 * 1024;   // N*S = 8192
constexpr int E    = 768;
constexpr int E3   = 2304;
constexpr int FF   = 3072;

// ---------------------------------------------------------------------------
// Scratch (device globals: allocation-guard safe)
// ---------------------------------------------------------------------------
__device__ float g_x1[(size_t)ROWS * E];
__device__ __half g_h[(size_t)ROWS * E];
__device__ __half g_attn[(size_t)ROWS * E];
__device__ __half g_ff[(size_t)ROWS * FF];
// Per-head QKV: [n(8)][h(12)][s(1024)][d(64)] fp16; Q pre-scaled by 0.125*log2(e)
__device__ __half g_q[(size_t)ROWS * E];
__device__ __half g_k[(size_t)ROWS * E];
__device__ __half g_v[(size_t)ROWS * E];
// Transposed fp16 weights: [N, K]
__device__ __half g_wqkv[(size_t)E3 * E];
__device__ __half g_wproj[(size_t)E * E];
__device__ __half g_wfc[(size_t)FF * E];
__device__ __half g_wfc2[(size_t)E * FF];

// ---------------------------------------------------------------------------
// Helpers (baseline compute_103 PTX: cp.async + mma.sync + ldmatrix)
// ---------------------------------------------------------------------------
__device__ __forceinline__ uint32_t smem_u32(const void* p) {
    uint32_t a;
    asm("{ .reg .u64 t; cvta.to.shared.u64 t, %1; cvt.u32.u64 %0, t; }" : "=r"(a) : "l"(p));
    return a;
}

#define CP_ASYNC16(dst, src) asm volatile("cp.async.cg.shared.global [%0], [%1], 16;" :: "r"(dst), "l"(src))
#define CP_COMMIT()          asm volatile("cp.async.commit_group;" ::: "memory")
#define CP_WAIT(n)           asm volatile("cp.async.wait_group %0;" :: "n"(n) : "memory")

#define MMA16816F16(d, a0, a1, a2, a3, b0, b1) \
    asm volatile( \
        "mma.sync.aligned.m16n8k16.row.col.f32.f16.f16.f32 " \
        "{%0,%1,%2,%3}, {%4,%5,%6,%7}, {%8,%9}, {%0,%1,%2,%3};" \
        : "+f"((d)[0]), "+f"((d)[1]), "+f"((d)[2]), "+f"((d)[3]) \
        : "r"(a0), "r"(a1), "r"(a2), "r"(a3), "r"(b0), "r"(b1))

#define LDMX4(r0, r1, r2, r3, addr) \
    asm volatile("ldmatrix.sync.aligned.m8n8.x4.shared.b16 {%0,%1,%2,%3}, [%4];" \
        : "=r"(r0), "=r"(r1), "=r"(r2), "=r"(r3) : "r"(addr))

#define LDMX4T(r0, r1, r2, r3, addr) \
    asm volatile("ldmatrix.sync.aligned.m8n8.x4.trans.shared.b16 {%0,%1,%2,%3}, [%4];" \
        : "=r"(r0), "=r"(r1), "=r"(r2), "=r"(r3) : "r"(addr))

__device__ __forceinline__ uint32_t packh2(float a, float b) {
    __half2 h = __floats2half2_rn(a, b);
    return *(uint32_t*)&h;
}

// ---------------------------------------------------------------------------
// LayerNorm -> fp16: one WARP per row, register-resident, shfl-only reduce.
// Grid 1024 x 256 threads (8 warps = 8 rows per block).
// ---------------------------------------------------------------------------
__global__ void __launch_bounds__(256) ln_kernel(const float* __restrict__ x,
                                                 const float* __restrict__ g,
                                                 const float* __restrict__ b,
                                                 __half* __restrict__ out) {
    int warp = threadIdx.x >> 5, lane = threadIdx.x & 31;
    int row = blockIdx.x * 8 + warp;
    const float4* xr = (const float4*)(x + (size_t)row * E);

    float4 v[6];
    float s = 0.f;
    #pragma unroll
    for (int i = 0; i < 6; i++) {
        v[i] = xr[lane + 32 * i];
        s += (v[i].x + v[i].y) + (v[i].z + v[i].w);
    }
    #pragma unroll
    for (int o = 16; o > 0; o >>= 1) s += __shfl_xor_sync(0xffffffffu, s, o);
    float mu = s * (1.0f / E);

    float sq = 0.f;
    #pragma unroll
    for (int i = 0; i < 6; i++) {
        v[i].x -= mu; v[i].y -= mu; v[i].z -= mu; v[i].w -= mu;
        sq += v[i].x * v[i].x + v[i].y * v[i].y + v[i].z * v[i].z + v[i].w * v[i].w;
    }
    #pragma unroll
    for (int o = 16; o > 0; o >>= 1) sq += __shfl_xor_sync(0xffffffffu, sq, o);
    float rs = rsqrtf(sq * (1.0f / E) + 1e-5f);

    const float4* gv = (const float4*)g;
    const float4* bv = (const float4*)b;
    uint2* orow = (uint2*)(out + (size_t)row * E);
    #pragma unroll
    for (int i = 0; i < 6; i++) {
        int j = lane + 32 * i;
        float4 gg = gv[j], bb = bv[j];
        float o0 = v[i].x * rs * gg.x + bb.x;
        float o1 = v[i].y * rs * gg.y + bb.y;
        float o2 = v[i].z * rs * gg.z + bb.z;
        float o3 = v[i].w * rs * gg.w + bb.w;
        uint2 pk;
        pk.x = packh2(o0, o1);
        pk.y = packh2(o2, o3);
        orow[j] = pk;
    }
}

// ---------------------------------------------------------------------------
// Fused weight transpose: all 4 weights in one launch.
// w[K,N] fp32 -> o[N,K] fp16.  Segment table by linear block id.
// ---------------------------------------------------------------------------
__global__ void __launch_bounds__(256) wsplit_all(
    const float* __restrict__ w0, const float* __restrict__ w1,
    const float* __restrict__ w2, const float* __restrict__ w3,
    __half* __restrict__ o0, __half* __restrict__ o1,
    __half* __restrict__ o2, __half* __restrict__ o3) {
    __shared__ float t[32][33];
    int blk = blockIdx.x;
    const float* w; __half* o; int K, N, bx, by;
    if (blk < 1728)      { blk -= 0;    w = w0; o = o0; K = 768;  N = 2304; bx = blk % 72; by = blk / 72; }
    else if (blk < 2304) { blk -= 1728; w = w1; o = o1; K = 768;  N = 768;  bx = blk % 24; by = blk / 24; }
    else if (blk < 4608) { blk -= 2304; w = w2; o = o2; K = 768;  N = 3072; bx = blk % 96; by = blk / 96; }
    else                 { blk -= 4608; w = w3; o = o3; K = 3072; N = 768;  bx = blk % 24; by = blk / 24; }
    int n0 = bx * 32, k0 = by * 32;
    int tx = threadIdx.x & 31, ty = threadIdx.x >> 5;
    #pragma unroll
    for (int j = 0; j < 32; j += 8)
        t[ty + j][tx] = w[(size_t)(k0 + ty + j) * N + n0 + tx];
    __syncthreads();
    #pragma unroll
    for (int j = 0; j < 32; j += 8)
        o[(size_t)(n0 + ty + j) * K + k0 + tx] = __float2half_rn(t[tx][ty + j]);
}

// ---------------------------------------------------------------------------
// fp16 mma.sync GEMM: C[M,N] = A[M,K] @ B[N,K]^T + bias (+epilogue)
// CTA 128x128, BK=32, 8 warps (4 M x 2 N), warp tile 32x64.
// 5-stage cp.async pipeline, ONE syncthreads per iter (prefetch target
// (it+4)%5 provably never collides with a buffer in use once all warps
// passed the top barrier). ldmatrix.x4 fragment loads, 80B padded rows.
// MODE 1: fp32 +bias+residual;  MODE 2: +bias, GELU -> fp16
// MODE 3: fp16 qkv scatter to per-head q/k/v (q scaled by 0.125*log2e)
// ---------------------------------------------------------------------------
constexpr int GBK = 32;
constexpr int TILE_B = 128 * 80;               // one subtile: 10240 B (80B rows)
constexpr int STAGE_B = 2 * TILE_B;            // A + B: 20480 B
constexpr int NSTAGE = 5;
constexpr size_t GEMM_SMEM = NSTAGE * STAGE_B; // 102400 B

template <int MODE>
__global__ void __launch_bounds__(256, 2) gemm_mma(
    const __half* __restrict__ A, const __half* __restrict__ B,
    const float* __restrict__ bias, const float* __restrict__ res,
    float* __restrict__ C, __half* __restrict__ Ch,
    __half* __restrict__ Qo, __half* __restrict__ Ko, __half* __restrict__ Vo,
    int Ndim, int Kdim) {
    extern __shared__ __align__(16) char smem[];
    uint32_t sb = smem_u32(smem);
    int tid = threadIdx.x, wid = tid >> 5, lane = tid & 31;
    int wm = wid & 3, wn = wid >> 2;           // warp grid 4 (M) x 2 (N)
    int m0 = blockIdx.y * 128, n0 = blockIdx.x * 128;
    int r = lane >> 2, c2 = (lane & 3) * 2;
    int lrow = lane & 15, lcol = (lane >> 4) * 16;

    float acc[2][8][4];
    #pragma unroll
    for (int mi = 0; mi < 2; mi++)
        #pragma unroll
        for (int ni = 0; ni < 8; ni++)
            #pragma unroll
            for (int q = 0; q < 4; q++) acc[mi][ni][q] = 0.f;

    auto load_stage = [&](int it, int buf) {
        int k0 = it * GBK;
        #pragma unroll
        for (int i = 0; i < 4; i++) {
            int ch = i * 256 + tid;
            int s = ch >> 9, cc = ch & 511;
            int row = cc >> 2, kc = cc & 3;
            uint32_t dst = sb + buf * STAGE_B + s * TILE_B + row * 80 + kc * 16;
            const __half* src = (s ? B + (size_t)(n0 + row) * Kdim
                                   : A + (size_t)(m0 + row) * Kdim) + k0 + kc * 8;
            CP_ASYNC16(dst, src);
        }
        CP_COMMIT();
    };

    load_stage(0, 0);
    load_stage(1, 1);
    load_stage(2, 2);
    load_stage(3, 3);

    int niter = Kdim / GBK;
    for (int it = 0; it < niter; ++it) {
        int buf = it % NSTAGE;
        if (it + 3 < niter) CP_WAIT(3);
        else if (it + 2 < niter) CP_WAIT(2);
        else if (it + 1 < niter) CP_WAIT(1);
        else CP_WAIT(0);
        __syncthreads();
        if (it + 4 < niter) load_stage(it + 4, (it + 4) % NSTAGE);

        uint32_t abase = sb + buf * STAGE_B;
        uint32_t bbase = abase + TILE_B;

        #pragma unroll
        for (int ks = 0; ks < 2; ks++) {
            uint32_t ah[2][4];
            #pragma unroll
            for (int mi = 0; mi < 2; mi++) {
                uint32_t addr = abase + (wm * 32 + mi * 16 + lrow) * 80 + ks * 32 + lcol;
                LDMX4(ah[mi][0], ah[mi][1], ah[mi][2], ah[mi][3], addr);
            }
            #pragma unroll
            for (int nb = 0; nb < 4; nb++) {
                uint32_t b0, b1, b2, b3;
                uint32_t addr = bbase + (wn * 64 + nb * 16 + lrow) * 80 + ks * 32 + lcol;
                LDMX4(b0, b1, b2, b3, addr);
                #pragma unroll
                for (int mi = 0; mi < 2; mi++) {
                    MMA16816F16(acc[mi][2 * nb],     ah[mi][0], ah[mi][1], ah[mi][2], ah[mi][3], b0, b2);
                    MMA16816F16(acc[mi][2 * nb + 1], ah[mi][0], ah[mi][1], ah[mi][2], ah[mi][3], b1, b3);
                }
            }
        }
    }

    // Epilogue: direct register writeout
    #pragma unroll
    for (int mi = 0; mi < 2; mi++) {
        #pragma unroll
        for (int ni = 0; ni < 8; ni++) {
            int row = m0 + wm * 32 + mi * 16 + r;
            int col = n0 + wn * 64 + ni * 8 + c2;
            float2 bv = *(const float2*)&bias[col];
            #pragma unroll
            for (int hf = 0; hf < 2; hf++) {
                int rr = row + hf * 8;
                float v0 = acc[mi][ni][hf * 2 + 0] + bv.x;
                float v1 = acc[mi][ni][hf * 2 + 1] + bv.y;
                if (MODE == 3) {
                    int which = col / 768;
                    int h = (col % 768) >> 6;
                    int d = col & 63;
                    size_t dst = ((size_t)((rr >> 10) * 12 + h) * 1024 + (rr & 1023)) * 64 + d;
                    __half* base = (which == 0) ? Qo : (which == 1) ? Ko : Vo;
                    float sc = (which == 0) ? 0.1803368823f : 1.0f;  // 0.125*log2(e)
                    *(__half2*)&base[dst] = __floats2half2_rn(v0 * sc, v1 * sc);
                } else {
                    size_t gi = (size_t)rr * Ndim + col;
                    if (MODE == 2) {
                        v0 = 0.5f * v0 * (1.0f + erff(v0 * 0.70710678118f));
                        v1 = 0.5f * v1 * (1.0f + erff(v1 * 0.70710678118f));
                        *(__half2*)&Ch[gi] = __floats2half2_rn(v0, v1);
                    } else {
                        float2 rv = *(const float2*)&res[gi];
                        v0 += rv.x; v1 += rv.y;
                        *(float2*)&C[gi] = make_float2(v0, v1);
                    }
                }
            }
        }
    }
}

// ---------------------------------------------------------------------------
// Tensor-core flash attention (fp16 mma, FA2-style).
// Grid (16 q-tiles, 96 n*h), 128 threads = 4 warps; warp w owns q-rows
// [w*16, w*16+16). KV tiles of 64, double-buffered cp.async.
// Q pre-scaled by 0.125*log2e; softmax via exp2f; P reused as fp16 A-frags.
// ---------------------------------------------------------------------------
constexpr int AQS = 72;                         // padded row stride (halves) = 144B
constexpr int ATT_TILE_B = 64 * AQS * 2;        // 9216 B
constexpr size_t ATT_SMEM = 5 * ATT_TILE_B;     // Q + 2*K + 2*V = 46080 B

__global__ void __launch_bounds__(128) attn_kernel() {
    extern __shared__ __align__(16) char smem[];
    uint32_t sb = smem_u32(smem);
    uint32_t Qb = sb;
    uint32_t Kb[2] = {sb + ATT_TILE_B, sb + 2 * ATT_TILE_B};
    uint32_t Vb[2] = {sb + 3 * ATT_TILE_B, sb + 4 * ATT_TILE_B};

    int qt = blockIdx.x;
    int nh = blockIdx.y;                        // n*12 + h
    size_t hbase = (size_t)nh * 1024 * 64;      // head base in g_q/g_k/g_v
    int n = nh / 12, h = nh % 12;
    int tid = threadIdx.x, wid = tid >> 5, lane = tid & 31;
    int r = lane >> 2, c2 = (lane & 3) * 2;
    int lrow = lane & 15, lcol = (lane >> 4) * 16;  // 16B units

    // tile loader: 64 rows x 128B, 512 chunks, 4/thread
    auto load_tile = [&](const __half* g, int t0, uint32_t dstb) {
        #pragma unroll
        for (int i = 0; i < 4; i++) {
            int ch = i * 128 + tid;
            int row = ch >> 3, kc = ch & 7;
            CP_ASYNC16(dstb + row * (AQS * 2) + kc * 16,
                       g + hbase + (size_t)(t0 + row) * 64 + kc * 8);
        }
        CP_COMMIT();
    };

    // Preload Q and first KV tile
    load_tile(g_q, qt * 64, Qb);
    load_tile(g_k, 0, Kb[0]);
    load_tile(g_v, 0, Vb[0]);
    CP_WAIT(0);
    __syncthreads();

    // Q fragments live in registers for the whole kernel: 4 k16-blocks
    uint32_t qf[4][4];
    #pragma unroll
    for (int kb = 0; kb < 4; kb++) {
        uint32_t addr = Qb + (wid * 16 + lrow) * (AQS * 2) + kb * 32 + lcol;
        LDMX4(qf[kb][0], qf[kb][1], qf[kb][2], qf[kb][3], addr);
    }

    float m0v = -1e30f, m1v = -1e30f, l0 = 0.f, l1 = 0.f;
    float o[8][4];
    #pragma unroll
    for (int db = 0; db < 8; db++)
        #pragma unroll
        for (int q = 0; q < 4; q++) o[db][q] = 0.f;

    for (int t = 0; t <= qt; ++t) {
        int buf = t & 1;
        if (t < qt) {
            load_tile(g_k, (t + 1) * 64, Kb[buf ^ 1]);
            load_tile(g_v, (t + 1) * 64, Vb[buf ^ 1]);
        }

        // S = Q @ K^T  (16 x 64 per warp)  — values are in log2 domain
        float s[8][4];
        #pragma unroll
        for (int nb = 0; nb < 8; nb++)
            #pragma unroll
            for (int q = 0; q < 4; q++) s[nb][q] = 0.f;
        #pragma unroll
        for (int kb = 0; kb < 4; kb++) {
            #pragma unroll
            for (int nb16 = 0; nb16 < 4; nb16++) {
                uint32_t b0, b1, b2, b3;
                uint32_t addr = Kb[buf] + (nb16 * 16 + lrow) * (AQS * 2) + kb * 32 + lcol;
                LDMX4(b0, b1, b2, b3, addr);
                MMA16816F16(s[nb16 * 2],     qf[kb][0], qf[kb][1], qf[kb][2], qf[kb][3], b0, b2);
                MMA16816F16(s[nb16 * 2 + 1], qf[kb][0], qf[kb][1], qf[kb][2], qf[kb][3], b1, b3);
            }
        }

        // Causal mask on diagonal tile
        if (t == qt) {
            int row0 = qt * 64 + wid * 16 + r;
            #pragma unroll
            for (int nb = 0; nb < 8; nb++) {
                int col = t * 64 + nb * 8 + c2;
                if (col > row0)     s[nb][0] = -1e30f;
                if (col + 1 > row0) s[nb][1] = -1e30f;
                if (col > row0 + 8)     s[nb][2] = -1e30f;
                if (col + 1 > row0 + 8) s[nb][3] = -1e30f;
            }
        }

        // Online softmax (rows r and r+8 of this warp's 16), exp2 domain
        float mx0 = -1e30f, mx1 = -1e30f;
        #pragma unroll
        for (int nb = 0; nb < 8; nb++) {
            mx0 = fmaxf(mx0, fmaxf(s[nb][0], s[nb][1]));
            mx1 = fmaxf(mx1, fmaxf(s[nb][2], s[nb][3]));
        }
        mx0 = fmaxf(mx0, __shfl_xor_sync(0xffffffffu, mx0, 1));
        mx0 = fmaxf(mx0, __shfl_xor_sync(0xffffffffu, mx0, 2));
        mx1 = fmaxf(mx1, __shfl_xor_sync(0xffffffffu, mx1, 1));
        mx1 = fmaxf(mx1, __shfl_xor_sync(0xffffffffu, mx1, 2));

        float nm0 = fmaxf(m0v, mx0), nm1 = fmaxf(m1v, mx1);
        float f0 = exp2f(m0v - nm0), f1 = exp2f(m1v - nm1);
        float ls0 = 0.f, ls1 = 0.f;
        #pragma unroll
        for (int nb = 0; nb < 8; nb++) {
            s[nb][0] = exp2f(s[nb][0] - nm0); ls0 += s[nb][0];
            s[nb][1] = exp2f(s[nb][1] - nm0); ls0 += s[nb][1];
            s[nb][2] = exp2f(s[nb][2] - nm1); ls1 += s[nb][2];
            s[nb][3] = exp2f(s[nb][3] - nm1); ls1 += s[nb][3];
        }
        l0 = l0 * f0 + ls0;      // per-lane partial; quad-reduced at end
        l1 = l1 * f1 + ls1;
        m0v = nm0; m1v = nm1;
        #pragma unroll
        for (int db = 0; db < 8; db++) {
            o[db][0] *= f0; o[db][1] *= f0;
            o[db][2] *= f1; o[db][3] *= f1;
        }

        // O += P @ V  (P fp16 from registers)
        #pragma unroll
        for (int kb2 = 0; kb2 < 4; kb2++) {
            uint32_t a0 = packh2(s[2 * kb2][0],     s[2 * kb2][1]);
            uint32_t a1 = packh2(s[2 * kb2][2],     s[2 * kb2][3]);
            uint32_t a2 = packh2(s[2 * kb2 + 1][0], s[2 * kb2 + 1][1]);
            uint32_t a3 = packh2(s[2 * kb2 + 1][2], s[2 * kb2 + 1][3]);
            #pragma unroll
            for (int db2 = 0; db2 < 4; db2++) {
                uint32_t v0, v1, v2, v3;
                uint32_t addr = Vb[buf] + (kb2 * 16 + lrow) * (AQS * 2) + db2 * 32 + lcol;
                LDMX4T(v0, v1, v2, v3, addr);
                MMA16816F16(o[db2 * 2],     a0, a1, a2, a3, v0, v1);
                MMA16816F16(o[db2 * 2 + 1], a0, a1, a2, a3, v2, v3);
            }
        }

        if (t < qt) {
            CP_WAIT(0);
            __syncthreads();
        }
    }

    // Reduce l over the quad, normalize, write fp16 [rows, E]
    l0 += __shfl_xor_sync(0xffffffffu, l0, 1);
    l0 += __shfl_xor_sync(0xffffffffu, l0, 2);
    l1 += __shfl_xor_sync(0xffffffffu, l1, 1);
    l1 += __shfl_xor_sync(0xffffffffu, l1, 2);
    float inv0 = 1.f / l0, inv1 = 1.f / l1;

    int row0 = n * 1024 + qt * 64 + wid * 16 + r;
    int colb = h * 64;
    #pragma unroll
    for (int db = 0; db < 8; db++) {
        size_t gi0 = (size_t)row0 * 768 + colb + db * 8 + c2;
        size_t gi1 = (size_t)(row0 + 8) * 768 + colb + db * 8 + c2;
        *(__half2*)&g_attn[gi0] = __floats2half2_rn(o[db][0] * inv0, o[db][1] * inv0);
        *(__half2*)&g_attn[gi1] = __floats2half2_rn(o[db][2] * inv1, o[db][3] * inv1);
    }
}

// ---------------------------------------------------------------------------
extern "C" void kernel_launch(void* const* d_in, const int* in_sizes, int n_in,
                              void* d_out, int out_size) {
    const float* x      = (const float*)d_in[0];
    const float* ln1_g  = (const float*)d_in[1];
    const float* ln1_b  = (const float*)d_in[2];
    const float* ln2_g  = (const float*)d_in[3];
    const float* ln2_b  = (const float*)d_in[4];
    const float* w_attn = (const float*)d_in[5];
    const float* b_attn = (const float*)d_in[6];
    const float* w_proj = (const float*)d_in[7];
    const float* b_proj = (const float*)d_in[8];
    const float* w_fc   = (const float*)d_in[9];
    const float* b_fc   = (const float*)d_in[10];
    const float* w_fc2  = (const float*)d_in[11];
    const float* b_fc2  = (const float*)d_in[12];
    float* out = (float*)d_out;

    float* p_x1;
    __half *p_h, *p_attn, *p_ff, *p_q, *p_k, *p_v;
    __half *p_wq, *p_wp, *p_wf, *p_w2;
    cudaGetSymbolAddress((void**)&p_x1, g_x1);
    cudaGetSymbolAddress((void**)&p_h, g_h);
    cudaGetSymbolAddress((void**)&p_attn, g_attn);
    cudaGetSymbolAddress((void**)&p_ff, g_ff);
    cudaGetSymbolAddress((void**)&p_q, g_q);
    cudaGetSymbolAddress((void**)&p_k, g_k);
    cudaGetSymbolAddress((void**)&p_v, g_v);
    cudaGetSymbolAddress((void**)&p_wq, g_wqkv);
    cudaGetSymbolAddress((void**)&p_wp, g_wproj);
    cudaGetSymbolAddress((void**)&p_wf, g_wfc);
    cudaGetSymbolAddress((void**)&p_w2, g_wfc2);

    cudaFuncSetAttribute(gemm_mma<1>, cudaFuncAttributeMaxDynamicSharedMemorySize, (int)GEMM_SMEM);
    cudaFuncSetAttribute(gemm_mma<2>, cudaFuncAttributeMaxDynamicSharedMemorySize, (int)GEMM_SMEM);
    cudaFuncSetAttribute(gemm_mma<3>, cudaFuncAttributeMaxDynamicSharedMemorySize, (int)GEMM_SMEM);
    cudaFuncSetAttribute(attn_kernel, cudaFuncAttributeMaxDynamicSharedMemorySize, (int)ATT_SMEM);

    // 0. all weight transposes in one launch
    wsplit_all<<<6912, 256>>>(w_attn, w_proj, w_fc, w_fc2, p_wq, p_wp, p_wf, p_w2);
    // 1. LN1 -> h (fp16)
    ln_kernel<<<1024, 256>>>(x, ln1_g, ln1_b, p_h);
    // 2. qkv GEMM -> per-head q/k/v fp16 (q scaled by 0.125*log2e)
    gemm_mma<3><<<dim3(18, 64), 256, GEMM_SMEM>>>(p_h, p_wq, b_attn, nullptr,
        nullptr, nullptr, p_q, p_k, p_v, E3, E);
    // 3. tensor-core causal flash attention -> attn (fp16 [rows, E])
    attn_kernel<<<dim3(16, 96), 128, ATT_SMEM>>>();
    // 4. x1 = x + attn @ w_proj + b_proj
    gemm_mma<1><<<dim3(6, 64), 256, GEMM_SMEM>>>(p_attn, p_wp, b_proj, x,
        p_x1, nullptr, nullptr, nullptr, nullptr, E, E);
    // 5. LN2 -> h (fp16)
    ln_kernel<<<1024, 256>>>(p_x1, ln2_g, ln2_b, p_h);
    // 6. ff = gelu(h @ w_fc + b_fc) -> fp16
    gemm_mma<2><<<dim3(24, 64), 256, GEMM_SMEM>>>(p_h, p_wf, b_fc, nullptr,
        nullptr, p_ff, nullptr, nullptr, nullptr, FF, E);
    // 7. out = x1 + ff @ w_fc2 + b_fc2
    gemm_mma<1><<<dim3(6, 64), 256, GEMM_SMEM>>>(p_ff, p_w2, b_fc2, p_x1,
        out, nullptr, nullptr, nullptr, nullptr, E, FF);
}